// round 8
// baseline (speedup 1.0000x reference)
#include <cuda_runtime.h>
#include <cuda_bf16.h>
#include <cstdint>

// Problem constants
#define BATCH 4
#define SEQ   2048
#define DMODEL 1024
#define NHEAD 16
#define HDIM  64
#define SCALE 0.25f

// ---------------------------------------------------------------------------
// Static device scratch
// ---------------------------------------------------------------------------
#define QKV_ELEMS ((size_t)BATCH * NHEAD * SEQ * HDIM)
__device__ __nv_bfloat16 g_Qhi[QKV_ELEMS];
__device__ __nv_bfloat16 g_Qlo[QKV_ELEMS];
__device__ __nv_bfloat16 g_Khi[QKV_ELEMS];
__device__ __nv_bfloat16 g_Klo[QKV_ELEMS];
__device__ __nv_bfloat16 g_Vthi[QKV_ELEMS];   // [B,H,HD,L] (transposed)
__device__ __nv_bfloat16 g_Vtlo[QKV_ELEMS];

// int8 two-limb operands for the projection GEMM
__device__ int8_t g_Xh8[(size_t)BATCH * SEQ * DMODEL];
__device__ int8_t g_Xl8[(size_t)BATCH * SEQ * DMODEL];
__device__ int8_t g_Wh8[(size_t)3 * DMODEL * DMODEL];
__device__ int8_t g_Wl8[(size_t)3 * DMODEL * DMODEL];
__device__ float  g_sX[BATCH * SEQ];
__device__ float  g_sW[3 * DMODEL];

// ---------------------------------------------------------------------------
// Helpers
// ---------------------------------------------------------------------------
__device__ __forceinline__ uint32_t smem_u32(const void* p) {
    uint32_t a;
    asm("{ .reg .u64 t; cvta.to.shared.u64 t, %1; cvt.u32.u64 %0, t; }"
        : "=r"(a) : "l"(p));
    return a;
}

__device__ __forceinline__ void cp16(uint32_t d, const void* s) {
    asm volatile("cp.async.cg.shared.global [%0], [%1], 16;" :: "r"(d), "l"(s) : "memory");
}
#define CP_COMMIT() asm volatile("cp.async.commit_group;" ::: "memory")
#define CP_WAIT(N)  asm volatile("cp.async.wait_group %0;" :: "n"(N) : "memory")

__device__ __forceinline__ uint32_t lds32(uint32_t a) {
    uint32_t v;
    asm volatile("ld.shared.b32 %0, [%1];" : "=r"(v) : "r"(a));
    return v;
}

__device__ __forceinline__ void mma16816(float* c, const uint32_t* a, const uint32_t* b) {
    asm volatile(
        "mma.sync.aligned.m16n8k16.row.col.f32.bf16.bf16.f32 "
        "{%0,%1,%2,%3}, {%4,%5,%6,%7}, {%8,%9}, {%0,%1,%2,%3};"
        : "+f"(c[0]), "+f"(c[1]), "+f"(c[2]), "+f"(c[3])
        : "r"(a[0]), "r"(a[1]), "r"(a[2]), "r"(a[3]), "r"(b[0]), "r"(b[1]));
}

__device__ __forceinline__ void imma16832(int* c, const uint32_t* a,
                                          uint32_t b0, uint32_t b1) {
    asm volatile(
        "mma.sync.aligned.m16n8k32.row.col.s32.s8.s8.s32 "
        "{%0,%1,%2,%3}, {%4,%5,%6,%7}, {%8,%9}, {%0,%1,%2,%3};"
        : "+r"(c[0]), "+r"(c[1]), "+r"(c[2]), "+r"(c[3])
        : "r"(a[0]), "r"(a[1]), "r"(a[2]), "r"(a[3]), "r"(b0), "r"(b1));
}

// Fast exp on the FMA pipe (x <= 0), rel err ~1e-5.
__device__ __forceinline__ float fexp(float x) {
    x = fmaxf(x, -87.0f);
    const float y = x * 1.44269504f;
    const float fl = floorf(y);
    const float f = y - fl;
    float p = 1.5403530e-4f;
    p = fmaf(p, f, 1.3333558e-3f);
    p = fmaf(p, f, 9.6181291e-3f);
    p = fmaf(p, f, 5.5504109e-2f);
    p = fmaf(p, f, 2.4022651e-1f);
    p = fmaf(p, f, 6.9314718e-1f);
    p = fmaf(p, f, 1.0f);
    return __int_as_float(__float_as_int(p) + (((int)fl) << 23));
}

__device__ __forceinline__ uint32_t pack_bf2(float x, float y) {
    __nv_bfloat162 t = __halves2bfloat162(__float2bfloat16(x), __float2bfloat16(y));
    return *(uint32_t*)&t;
}

// ---------------------------------------------------------------------------
// Row quantization: fp32 row (1024) -> two int8 limbs + scale.
// v = round(x*32639/max), h = (v+128)>>8, l = v - 256h. x ~= s*(256h + l).
// ---------------------------------------------------------------------------
__global__ __launch_bounds__(128) void quant_kernel(
    const float* __restrict__ src,
    int8_t* __restrict__ h8, int8_t* __restrict__ l8,
    float* __restrict__ scale)
{
    const int row = blockIdx.x;
    const float* x = src + (size_t)row * DMODEL;
    const int tid = threadIdx.x;
    float vals[8];
    float mx = 0.0f;
    #pragma unroll
    for (int i = 0; i < 8; ++i) {
        vals[i] = x[tid + 128 * i];
        mx = fmaxf(mx, fabsf(vals[i]));
    }
    #pragma unroll
    for (int o = 16; o >= 1; o >>= 1)
        mx = fmaxf(mx, __shfl_xor_sync(0xffffffffu, mx, o));
    __shared__ float sm[4];
    if ((tid & 31) == 0) sm[tid >> 5] = mx;
    __syncthreads();
    mx = fmaxf(fmaxf(sm[0], sm[1]), fmaxf(sm[2], sm[3]));
    mx = fmaxf(mx, 1e-30f);
    if (tid == 0) scale[row] = mx * (1.0f / 32639.0f);
    const float inv = 32639.0f / mx;
    #pragma unroll
    for (int i = 0; i < 8; ++i) {
        const int v = __float2int_rn(vals[i] * inv);
        const int h = (v + 128) >> 8;
        const int l = v - (h << 8);
        h8[(size_t)row * DMODEL + tid + 128 * i] = (int8_t)h;
        l8[(size_t)row * DMODEL + tid + 128 * i] = (int8_t)l;
    }
}

// ---------------------------------------------------------------------------
// int8 two-limb projection GEMM: C = X @ W^T + bias.
// CTA 128x128, 8 warps (4x2), warp tile 32x64. K-chunks of 64 (2 IMMA k-steps),
// double-buffered cp.async. 3 limb-term IMMAs (hh -> acc1, hl+lh -> acc2).
// Epilogue: dequant, bias, fp32 -> bf16 hi/lo, scatter Q,K [B,H,L,HD];
// V transposed [B,H,HD,L].
// ---------------------------------------------------------------------------
#define PITCH8 80                        // bytes per smem row (64 data + 16 pad)
#define ARR8 (128 * PITCH8)              // 10240
#define STG8 (4 * ARR8)                  // 40960 (Ah, Al, Bh, Bl)
#define GEMM_SMEM (2 * STG8)             // 81920

__device__ __forceinline__ void load_stage8(
    uint32_t stg, const int8_t* __restrict__ Xh, const int8_t* __restrict__ Xl,
    const int8_t* __restrict__ Wh, const int8_t* __restrict__ Wl,
    int rowBase, int colBase, int k0, int tid)
{
    #pragma unroll
    for (int it = 0; it < 8; ++it) {
        const int u = tid + it * 256;
        const int arr = u >> 9;            // 512 cp16 per array
        const int r = (u >> 2) & 127;
        const int cc = u & 3;
        const int8_t* src;
        if (arr == 0)      src = Xh + (size_t)(rowBase + r) * DMODEL + k0 + cc * 16;
        else if (arr == 1) src = Xl + (size_t)(rowBase + r) * DMODEL + k0 + cc * 16;
        else if (arr == 2) src = Wh + (size_t)(colBase + r) * DMODEL + k0 + cc * 16;
        else               src = Wl + (size_t)(colBase + r) * DMODEL + k0 + cc * 16;
        cp16(stg + arr * ARR8 + r * PITCH8 + cc * 16, src);
    }
}

__global__ __launch_bounds__(256) void gemm_kernel(
    const float* __restrict__ bq, const float* __restrict__ bk,
    const float* __restrict__ bv)
{
    extern __shared__ char smem[];
    const uint32_t sb = smem_u32(smem);
    const int tid = threadIdx.x;
    const int warp = tid >> 5;
    const int lane = tid & 31;
    const int g = lane >> 2;
    const int c = lane & 3;
    const int wm = warp >> 1;
    const int wn = warp & 1;

    const int which = blockIdx.z;
    const int8_t* Wh = g_Wh8 + (size_t)which * DMODEL * DMODEL;
    const int8_t* Wl = g_Wl8 + (size_t)which * DMODEL * DMODEL;
    const float* sw = g_sW + which * DMODEL;
    const float* bias = (which == 0) ? bq : (which == 1) ? bk : bv;
    __nv_bfloat16* oh = (which == 0) ? g_Qhi : (which == 1) ? g_Khi : g_Vthi;
    __nv_bfloat16* ol = (which == 0) ? g_Qlo : (which == 1) ? g_Klo : g_Vtlo;

    const int rowBase = blockIdx.x * 128;
    const int colBase = blockIdx.y * 128;

    int hh[2][8][4] = {};
    int mm[2][8][4] = {};

    load_stage8(sb, g_Xh8, g_Xl8, Wh, Wl, rowBase, colBase, 0, tid);
    CP_COMMIT();

    const uint32_t aB = (uint32_t)(wm * 32 + g) * PITCH8 + 4 * c;
    const uint32_t bB = (uint32_t)(wn * 64 + g) * PITCH8 + 4 * c;

    for (int sidx = 0; sidx < DMODEL / 64; ++sidx) {
        const uint32_t stg = sb + (uint32_t)(sidx & 1) * STG8;
        if (sidx + 1 < DMODEL / 64) {
            load_stage8(sb + (uint32_t)((sidx + 1) & 1) * STG8,
                        g_Xh8, g_Xl8, Wh, Wl, rowBase, colBase, (sidx + 1) * 64, tid);
            CP_COMMIT();
            CP_WAIT(1);
        } else {
            CP_WAIT(0);
        }
        __syncthreads();

        #pragma unroll
        for (int ks = 0; ks < 2; ++ks) {
            const uint32_t ko = ks * 32;
            uint32_t ah[2][4], al[2][4];
            #pragma unroll
            for (int mt = 0; mt < 2; ++mt) {
                const uint32_t ba = stg + aB + mt * 16 * PITCH8 + ko;
                ah[mt][0] = lds32(ba);
                ah[mt][1] = lds32(ba + 8 * PITCH8);
                ah[mt][2] = lds32(ba + 16);
                ah[mt][3] = lds32(ba + 8 * PITCH8 + 16);
                const uint32_t bal = ba + ARR8;
                al[mt][0] = lds32(bal);
                al[mt][1] = lds32(bal + 8 * PITCH8);
                al[mt][2] = lds32(bal + 16);
                al[mt][3] = lds32(bal + 8 * PITCH8 + 16);
            }
            #pragma unroll
            for (int nt = 0; nt < 8; ++nt) {
                const uint32_t bb = stg + 2 * ARR8 + bB + nt * 8 * PITCH8 + ko;
                const uint32_t bh0 = lds32(bb);
                const uint32_t bh1 = lds32(bb + 16);
                const uint32_t bl0 = lds32(bb + ARR8);
                const uint32_t bl1 = lds32(bb + ARR8 + 16);
                #pragma unroll
                for (int mt = 0; mt < 2; ++mt) {
                    imma16832(hh[mt][nt], ah[mt], bh0, bh1);
                    imma16832(mm[mt][nt], ah[mt], bl0, bl1);
                    imma16832(mm[mt][nt], al[mt], bh0, bh1);
                }
            }
        }
        __syncthreads();
    }

    // Epilogue: dequant + bias, fp32 -> bf16 hi/lo, scatter
    #pragma unroll
    for (int mt = 0; mt < 2; ++mt) {
        const int row0 = rowBase + wm * 32 + mt * 16 + g;
        #pragma unroll
        for (int nt = 0; nt < 8; ++nt) {
            const int col = colBase + wn * 64 + nt * 8 + 2 * c;
            const float swx = __ldg(&sw[col]);
            const float swy = __ldg(&sw[col + 1]);
            const float bx = __ldg(&bias[col]);
            const float by = __ldg(&bias[col + 1]);
            const int h = col >> 6, hd = col & 63;
            #pragma unroll
            for (int half = 0; half < 2; ++half) {
                const int row = row0 + half * 8;
                const int b = row >> 11, s = row & 2047;
                const float sxr = __ldg(&g_sX[row]);
                const float vx = sxr * swx *
                    fmaf(65536.0f, (float)hh[mt][nt][half * 2 + 0],
                         256.0f * (float)mm[mt][nt][half * 2 + 0]) + bx;
                const float vy = sxr * swy *
                    fmaf(65536.0f, (float)hh[mt][nt][half * 2 + 1],
                         256.0f * (float)mm[mt][nt][half * 2 + 1]) + by;
                const __nv_bfloat16 hx = __float2bfloat16(vx);
                const __nv_bfloat16 hy = __float2bfloat16(vy);
                const __nv_bfloat16 lx = __float2bfloat16(vx - __bfloat162float(hx));
                const __nv_bfloat16 ly = __float2bfloat16(vy - __bfloat162float(hy));
                if (which < 2) {
                    const size_t o = (((size_t)b * NHEAD + h) * SEQ + s) * HDIM + hd;
                    *(__nv_bfloat162*)&oh[o] = __halves2bfloat162(hx, hy);
                    *(__nv_bfloat162*)&ol[o] = __halves2bfloat162(lx, ly);
                } else {
                    const size_t o = (((size_t)b * NHEAD + h) * HDIM + hd) * SEQ + s;
                    oh[o] = hx; oh[o + SEQ] = hy;
                    ol[o] = lx; ol[o + SEQ] = ly;
                }
            }
        }
    }
}

// ---------------------------------------------------------------------------
// Tensor-core flash attention (causal). CTA = 64 q-rows, 4 warps (m16 each).
// S and P·V via mma.sync with split-bf16 3-term; P stays in registers.
// (Unchanged from R7.)
// ---------------------------------------------------------------------------
#define AP2 144
#define TILEB (64 * AP2)
#define KHI_O 0
#define KLO_O TILEB
#define VHI_O (2 * TILEB)
#define VLO_O (3 * TILEB)
#define ASTGB (4 * TILEB)
#define ATT_SMEM (2 * ASTGB)

__device__ __forceinline__ void load_kv_tile(uint32_t stg, int bh, int key0, int tid)
{
    const __nv_bfloat16* kh = g_Khi + ((size_t)bh * SEQ + key0) * HDIM;
    const __nv_bfloat16* kl = g_Klo + ((size_t)bh * SEQ + key0) * HDIM;
    const __nv_bfloat16* vh = g_Vthi + (size_t)bh * HDIM * SEQ + key0;
    const __nv_bfloat16* vl = g_Vtlo + (size_t)bh * HDIM * SEQ + key0;
    #pragma unroll
    for (int it = 0; it < 4; ++it) {
        const int u = tid + it * 128;
        const int r = u >> 3, cc = u & 7;
        cp16(stg + KHI_O + r * AP2 + cc * 16, kh + r * HDIM + cc * 8);
        cp16(stg + KLO_O + r * AP2 + cc * 16, kl + r * HDIM + cc * 8);
        cp16(stg + VHI_O + r * AP2 + cc * 16, vh + (size_t)r * SEQ + cc * 8);
        cp16(stg + VLO_O + r * AP2 + cc * 16, vl + (size_t)r * SEQ + cc * 8);
    }
}

__global__ __launch_bounds__(128) void attn_kernel(float* __restrict__ out)
{
    extern __shared__ char smemc[];
    const uint32_t sb = smem_u32(smemc);
    const int tid = threadIdx.x;
    const int warp = tid >> 5;
    const int lane = tid & 31;
    const int g = lane >> 2;
    const int c = lane & 3;
    const int moff = warp * 16;

    const int bh = blockIdx.y;
    const int b = bh >> 4;
    const int h = bh & 15;
    const int qi = (SEQ / 64 - 1) - blockIdx.x;

    {
        const __nv_bfloat16* qh = g_Qhi + ((size_t)bh * SEQ + (size_t)qi * 64) * HDIM;
        const __nv_bfloat16* ql = g_Qlo + ((size_t)bh * SEQ + (size_t)qi * 64) * HDIM;
        #pragma unroll
        for (int it = 0; it < 4; ++it) {
            const int u = tid + it * 128;
            const int r = u >> 3, cc = u & 7;
            cp16(sb + ASTGB + KHI_O + r * AP2 + cc * 16, qh + r * HDIM + cc * 8);
            cp16(sb + ASTGB + KLO_O + r * AP2 + cc * 16, ql + r * HDIM + cc * 8);
        }
        CP_COMMIT();
        load_kv_tile(sb, bh, 0, tid);
        CP_COMMIT();
    }

    uint32_t qhi[4][4], qlo[4][4];
    CP_WAIT(1);
    __syncthreads();
    {
        const uint32_t qb = sb + ASTGB + KHI_O + (uint32_t)(moff + g) * AP2 + c * 4;
        #pragma unroll
        for (int kt = 0; kt < 4; ++kt) {
            qhi[kt][0] = lds32(qb + kt * 32);
            qhi[kt][1] = lds32(qb + kt * 32 + 8 * AP2);
            qhi[kt][2] = lds32(qb + kt * 32 + 16);
            qhi[kt][3] = lds32(qb + kt * 32 + 8 * AP2 + 16);
            qlo[kt][0] = lds32(qb + TILEB + kt * 32);
            qlo[kt][1] = lds32(qb + TILEB + kt * 32 + 8 * AP2);
            qlo[kt][2] = lds32(qb + TILEB + kt * 32 + 16);
            qlo[kt][3] = lds32(qb + TILEB + kt * 32 + 8 * AP2 + 16);
        }
    }
    __syncthreads();

    float O[8][4] = {};
    float m[2] = {-1e30f, -1e30f};
    float l[2] = {0.0f, 0.0f};

    for (int jb = 0; jb <= qi; ++jb) {
        const uint32_t stg = sb + (uint32_t)(jb & 1) * ASTGB;
        if (jb < qi) {
            load_kv_tile(sb + (uint32_t)((jb + 1) & 1) * ASTGB, bh, (jb + 1) * 64, tid);
            CP_COMMIT();
            CP_WAIT(1);
        } else {
            CP_WAIT(0);
        }
        __syncthreads();

        float S[8][4] = {};
        #pragma unroll
        for (int kt = 0; kt < 4; ++kt) {
            uint32_t bhf[8][2], blf[8][2];
            const uint32_t kb = stg + KHI_O + (uint32_t)g * AP2 + kt * 32 + c * 4;
            #pragma unroll
            for (int nt = 0; nt < 8; ++nt) {
                const uint32_t a0 = kb + nt * 8 * AP2;
                bhf[nt][0] = lds32(a0);
                bhf[nt][1] = lds32(a0 + 16);
                blf[nt][0] = lds32(a0 + TILEB);
                blf[nt][1] = lds32(a0 + TILEB + 16);
            }
            #pragma unroll
            for (int nt = 0; nt < 8; ++nt) mma16816(S[nt], qhi[kt], bhf[nt]);
            #pragma unroll
            for (int nt = 0; nt < 8; ++nt) mma16816(S[nt], qhi[kt], blf[nt]);
            #pragma unroll
            for (int nt = 0; nt < 8; ++nt) mma16816(S[nt], qlo[kt], bhf[nt]);
        }

        const bool diag = (jb == qi);
        #pragma unroll
        for (int nt = 0; nt < 8; ++nt) {
            #pragma unroll
            for (int e = 0; e < 4; ++e) {
                float v = S[nt][e] * SCALE;
                if (diag) {
                    const int col = nt * 8 + 2 * c + (e & 1);
                    const int row = moff + g + ((e >> 1) << 3);
                    if (col > row) v = -1e30f;
                }
                S[nt][e] = v;
            }
        }

        float rowm[2] = {-1e30f, -1e30f};
        #pragma unroll
        for (int nt = 0; nt < 8; ++nt) {
            rowm[0] = fmaxf(rowm[0], fmaxf(S[nt][0], S[nt][1]));
            rowm[1] = fmaxf(rowm[1], fmaxf(S[nt][2], S[nt][3]));
        }
        #pragma unroll
        for (int r = 0; r < 2; ++r) {
            rowm[r] = fmaxf(rowm[r], __shfl_xor_sync(0xffffffffu, rowm[r], 1));
            rowm[r] = fmaxf(rowm[r], __shfl_xor_sync(0xffffffffu, rowm[r], 2));
        }
        float corr[2];
        #pragma unroll
        for (int r = 0; r < 2; ++r) {
            const float mnew = fmaxf(m[r], rowm[r]);
            corr[r] = fexp(m[r] - mnew);
            l[r] *= corr[r];
            m[r] = mnew;
        }
        #pragma unroll
        for (int nt = 0; nt < 8; ++nt) {
            O[nt][0] *= corr[0]; O[nt][1] *= corr[0];
            O[nt][2] *= corr[1]; O[nt][3] *= corr[1];
        }
        float psum[2] = {0.0f, 0.0f};
        #pragma unroll
        for (int nt = 0; nt < 8; ++nt) {
            #pragma unroll
            for (int e = 0; e < 4; ++e) {
                const float p = fexp(S[nt][e] - m[e >> 1]);
                S[nt][e] = p;
                psum[e >> 1] += p;
            }
        }
        #pragma unroll
        for (int r = 0; r < 2; ++r) {
            psum[r] += __shfl_xor_sync(0xffffffffu, psum[r], 1);
            psum[r] += __shfl_xor_sync(0xffffffffu, psum[r], 2);
            l[r] += psum[r];
        }

        uint32_t phi[4][4], plo[4][4];
        #pragma unroll
        for (int t = 0; t < 8; ++t) {
            const int kt = t >> 1;
            const int sl = (t & 1) << 1;
            float h01x = __bfloat162float(__float2bfloat16(S[t][0]));
            float h01y = __bfloat162float(__float2bfloat16(S[t][1]));
            float h23x = __bfloat162float(__float2bfloat16(S[t][2]));
            float h23y = __bfloat162float(__float2bfloat16(S[t][3]));
            phi[kt][sl + 0] = pack_bf2(h01x, h01y);
            phi[kt][sl + 1] = pack_bf2(h23x, h23y);
            plo[kt][sl + 0] = pack_bf2(S[t][0] - h01x, S[t][1] - h01y);
            plo[kt][sl + 1] = pack_bf2(S[t][2] - h23x, S[t][3] - h23y);
        }

        #pragma unroll
        for (int kt = 0; kt < 4; ++kt) {
            uint32_t vhf[8][2], vlf[8][2];
            const uint32_t vb = stg + VHI_O + (uint32_t)g * AP2 + kt * 32 + c * 4;
            #pragma unroll
            for (int nt = 0; nt < 8; ++nt) {
                const uint32_t a0 = vb + nt * 8 * AP2;
                vhf[nt][0] = lds32(a0);
                vhf[nt][1] = lds32(a0 + 16);
                vlf[nt][0] = lds32(a0 + TILEB);
                vlf[nt][1] = lds32(a0 + TILEB + 16);
            }
            #pragma unroll
            for (int nt = 0; nt < 8; ++nt) mma16816(O[nt], phi[kt], vhf[nt]);
            #pragma unroll
            for (int nt = 0; nt < 8; ++nt) mma16816(O[nt], phi[kt], vlf[nt]);
            #pragma unroll
            for (int nt = 0; nt < 8; ++nt) mma16816(O[nt], plo[kt], vhf[nt]);
        }
        __syncthreads();
    }

    const float inv0 = 1.0f / l[0];
    const float inv1 = 1.0f / l[1];
    const int row0 = qi * 64 + moff + g;
    #pragma unroll
    for (int nt = 0; nt < 8; ++nt) {
        const int col = h * HDIM + nt * 8 + 2 * c;
        float2 v0 = {O[nt][0] * inv0, O[nt][1] * inv0};
        float2 v1 = {O[nt][2] * inv1, O[nt][3] * inv1};
        *(float2*)&out[((size_t)b * SEQ + row0) * DMODEL + col] = v0;
        *(float2*)&out[((size_t)b * SEQ + row0 + 8) * DMODEL + col] = v1;
    }
}

// ---------------------------------------------------------------------------
extern "C" void kernel_launch(void* const* d_in, const int* in_sizes, int n_in,
                              void* d_out, int out_size)
{
    const float* X  = (const float*)d_in[0];
    const float* Wq = (const float*)d_in[1];
    const float* bq = (const float*)d_in[2];
    const float* Wk = (const float*)d_in[3];
    const float* bk = (const float*)d_in[4];
    const float* Wv = (const float*)d_in[5];
    const float* bv = (const float*)d_in[6];
    float* out = (float*)d_out;

    int8_t *xh8, *xl8, *wh8, *wl8;
    float *sx, *swp;
    cudaGetSymbolAddress((void**)&xh8, g_Xh8);
    cudaGetSymbolAddress((void**)&xl8, g_Xl8);
    cudaGetSymbolAddress((void**)&wh8, g_Wh8);
    cudaGetSymbolAddress((void**)&wl8, g_Wl8);
    cudaGetSymbolAddress((void**)&sx, g_sX);
    cudaGetSymbolAddress((void**)&swp, g_sW);

    const size_t wsz = (size_t)DMODEL * DMODEL;
    quant_kernel<<<BATCH * SEQ, 128>>>(X, xh8, xl8, sx);
    quant_kernel<<<DMODEL, 128>>>(Wq, wh8 + 0 * wsz, wl8 + 0 * wsz, swp + 0 * DMODEL);
    quant_kernel<<<DMODEL, 128>>>(Wk, wh8 + 1 * wsz, wl8 + 1 * wsz, swp + 1 * DMODEL);
    quant_kernel<<<DMODEL, 128>>>(Wv, wh8 + 2 * wsz, wl8 + 2 * wsz, swp + 2 * DMODEL);

    cudaFuncSetAttribute(gemm_kernel, cudaFuncAttributeMaxDynamicSharedMemorySize,
                         GEMM_SMEM);
    dim3 gg((BATCH * SEQ) / 128, DMODEL / 128, 3);
    gemm_kernel<<<gg, 256, GEMM_SMEM>>>(bq, bk, bv);

    cudaFuncSetAttribute(attn_kernel, cudaFuncAttributeMaxDynamicSharedMemorySize,
                         ATT_SMEM);
    dim3 ag(SEQ / 64, BATCH * NHEAD);
    attn_kernel<<<ag, 128, ATT_SMEM>>>(out);
}

// round 10
// speedup vs baseline: 3.1426x; 3.1426x over previous
#include <cuda_runtime.h>
#include <cuda_bf16.h>
#include <cuda_fp16.h>
#include <cstdint>

// Problem constants
#define BATCH 4
#define SEQ   2048
#define DMODEL 1024
#define NHEAD 16
#define HDIM  64
#define SCALE 0.25f

// ---------------------------------------------------------------------------
// Static device scratch
// ---------------------------------------------------------------------------
#define QKV_ELEMS ((size_t)BATCH * NHEAD * SEQ * HDIM)
__device__ __nv_bfloat16 g_Qhi[QKV_ELEMS];
__device__ __nv_bfloat16 g_Qlo[QKV_ELEMS];
__device__ __nv_bfloat16 g_Khi[QKV_ELEMS];
__device__ __nv_bfloat16 g_Klo[QKV_ELEMS];
__device__ __half        g_Vthi[QKV_ELEMS];   // [B,H,HD,L] transposed, fp16 limbs
__device__ __half        g_Vtlo[QKV_ELEMS];

__device__ __nv_bfloat16 g_Xhi[(size_t)BATCH * SEQ * DMODEL];
__device__ __nv_bfloat16 g_Xlo[(size_t)BATCH * SEQ * DMODEL];
__device__ __nv_bfloat16 g_Whi[(size_t)3 * DMODEL * DMODEL];
__device__ __nv_bfloat16 g_Wlo[(size_t)3 * DMODEL * DMODEL];

// ---------------------------------------------------------------------------
// Helpers
// ---------------------------------------------------------------------------
__device__ __forceinline__ uint32_t smem_u32(const void* p) {
    uint32_t a;
    asm("{ .reg .u64 t; cvta.to.shared.u64 t, %1; cvt.u32.u64 %0, t; }"
        : "=r"(a) : "l"(p));
    return a;
}

__device__ __forceinline__ void cp16(uint32_t d, const void* s) {
    asm volatile("cp.async.cg.shared.global [%0], [%1], 16;" :: "r"(d), "l"(s) : "memory");
}
#define CP_COMMIT() asm volatile("cp.async.commit_group;" ::: "memory")
#define CP_WAIT(N)  asm volatile("cp.async.wait_group %0;" :: "n"(N) : "memory")

__device__ __forceinline__ uint32_t lds32(uint32_t a) {
    uint32_t v;
    asm volatile("ld.shared.b32 %0, [%1];" : "=r"(v) : "r"(a));
    return v;
}

// bf16 mma: m16n8k16 -> f32
__device__ __forceinline__ void mma16816(float* c, const uint32_t* a, const uint32_t* b) {
    asm volatile(
        "mma.sync.aligned.m16n8k16.row.col.f32.bf16.bf16.f32 "
        "{%0,%1,%2,%3}, {%4,%5,%6,%7}, {%8,%9}, {%0,%1,%2,%3};"
        : "+f"(c[0]), "+f"(c[1]), "+f"(c[2]), "+f"(c[3])
        : "r"(a[0]), "r"(a[1]), "r"(a[2]), "r"(a[3]), "r"(b[0]), "r"(b[1]));
}

// fp16 mma: m16n8k16 -> f32
__device__ __forceinline__ void mma16816h(float* c, const uint32_t* a,
                                          uint32_t b0, uint32_t b1) {
    asm volatile(
        "mma.sync.aligned.m16n8k16.row.col.f32.f16.f16.f32 "
        "{%0,%1,%2,%3}, {%4,%5,%6,%7}, {%8,%9}, {%0,%1,%2,%3};"
        : "+f"(c[0]), "+f"(c[1]), "+f"(c[2]), "+f"(c[3])
        : "r"(a[0]), "r"(a[1]), "r"(a[2]), "r"(a[3]), "r"(b0), "r"(b1));
}

// Fast exp on the FMA pipe (x <= 0), rel err ~1e-5.
__device__ __forceinline__ float fexp(float x) {
    x = fmaxf(x, -87.0f);
    const float y = x * 1.44269504f;
    const float fl = floorf(y);
    const float f = y - fl;
    float p = 1.5403530e-4f;
    p = fmaf(p, f, 1.3333558e-3f);
    p = fmaf(p, f, 9.6181291e-3f);
    p = fmaf(p, f, 5.5504109e-2f);
    p = fmaf(p, f, 2.4022651e-1f);
    p = fmaf(p, f, 6.9314718e-1f);
    p = fmaf(p, f, 1.0f);
    return __int_as_float(__float_as_int(p) + (((int)fl) << 23));
}

__device__ __forceinline__ uint32_t pack_h2(float x, float y) {
    __half2 t = __halves2half2(__float2half(x), __float2half(y));
    return *(uint32_t*)&t;
}

// ---------------------------------------------------------------------------
// Split fp32 -> (bf16 hi, bf16 lo)
// ---------------------------------------------------------------------------
__global__ __launch_bounds__(256) void split_kernel(
    const float* __restrict__ src,
    __nv_bfloat16* __restrict__ hi, __nv_bfloat16* __restrict__ lo)
{
    const int i = blockIdx.x * 256 + threadIdx.x;
    float4 v = ((const float4*)src)[i];
    float a[4] = {v.x, v.y, v.z, v.w};
    __nv_bfloat16 h[4], l[4];
    #pragma unroll
    for (int j = 0; j < 4; ++j) {
        h[j] = __float2bfloat16(a[j]);
        l[j] = __float2bfloat16(a[j] - __bfloat162float(h[j]));
    }
    ((__nv_bfloat162*)hi)[2 * i + 0] = __halves2bfloat162(h[0], h[1]);
    ((__nv_bfloat162*)hi)[2 * i + 1] = __halves2bfloat162(h[2], h[3]);
    ((__nv_bfloat162*)lo)[2 * i + 0] = __halves2bfloat162(l[0], l[1]);
    ((__nv_bfloat162*)lo)[2 * i + 1] = __halves2bfloat162(l[2], l[3]);
}

// ---------------------------------------------------------------------------
// mma.sync projection GEMM: C = X @ W^T + bias, split-bf16 3-term.
// Epilogue: Q,K bf16 hi/lo [B,H,L,HD]; V fp16 hi/lo transposed [B,H,HD,L].
// ---------------------------------------------------------------------------
#define PITCH 40
#define ARR_BYTES (128 * PITCH * 2)
#define STG_BYTES (4 * ARR_BYTES)
#define GEMM_SMEM (2 * STG_BYTES)

__device__ __forceinline__ void load_stage(
    uint32_t stg, const __nv_bfloat16* __restrict__ Xh,
    const __nv_bfloat16* __restrict__ Xl,
    const __nv_bfloat16* __restrict__ Wh,
    const __nv_bfloat16* __restrict__ Wl,
    int rowBase, int colBase, int k0, int tid)
{
    #pragma unroll
    for (int it = 0; it < 8; ++it) {
        const int u = tid + it * 256;
        const int arr = it >> 1;
        const int r = (u >> 2) & 127;
        const int cc = u & 3;
        const __nv_bfloat16* src;
        if (arr == 0)      src = Xh + (size_t)(rowBase + r) * DMODEL + k0 + cc * 8;
        else if (arr == 1) src = Xl + (size_t)(rowBase + r) * DMODEL + k0 + cc * 8;
        else if (arr == 2) src = Wh + (size_t)(colBase + r) * DMODEL + k0 + cc * 8;
        else               src = Wl + (size_t)(colBase + r) * DMODEL + k0 + cc * 8;
        cp16(stg + arr * ARR_BYTES + r * (PITCH * 2) + cc * 16, src);
    }
}

__global__ __launch_bounds__(256) void gemm_kernel(
    const float* __restrict__ bq, const float* __restrict__ bk,
    const float* __restrict__ bv)
{
    extern __shared__ char smem[];
    const uint32_t sb = smem_u32(smem);
    const int tid = threadIdx.x;
    const int warp = tid >> 5;
    const int lane = tid & 31;
    const int g = lane >> 2;
    const int c = lane & 3;
    const int wm = warp >> 1;
    const int wn = warp & 1;

    const int which = blockIdx.z;
    const __nv_bfloat16* Wh = g_Whi + (size_t)which * DMODEL * DMODEL;
    const __nv_bfloat16* Wl = g_Wlo + (size_t)which * DMODEL * DMODEL;
    const float* bias = (which == 0) ? bq : (which == 1) ? bk : bv;
    __nv_bfloat16* oh = (which == 0) ? g_Qhi : g_Khi;
    __nv_bfloat16* ol = (which == 0) ? g_Qlo : g_Klo;

    const int rowBase = blockIdx.x * 128;
    const int colBase = blockIdx.y * 128;

    float acc[2][8][4] = {};

    load_stage(sb, g_Xhi, g_Xlo, Wh, Wl, rowBase, colBase, 0, tid);
    CP_COMMIT();

    const uint32_t aRowB = (uint32_t)(wm * 32 + g) * (PITCH * 2) + c * 4;
    const uint32_t bColB = (uint32_t)(wn * 64 + g) * (PITCH * 2) + c * 4;

    for (int sidx = 0; sidx < DMODEL / 32; ++sidx) {
        const uint32_t stg = sb + (uint32_t)(sidx & 1) * STG_BYTES;
        if (sidx + 1 < DMODEL / 32) {
            load_stage(sb + (uint32_t)((sidx + 1) & 1) * STG_BYTES,
                       g_Xhi, g_Xlo, Wh, Wl, rowBase, colBase, (sidx + 1) * 32, tid);
            CP_COMMIT();
            CP_WAIT(1);
        } else {
            CP_WAIT(0);
        }
        __syncthreads();

        #pragma unroll
        for (int kk = 0; kk < 2; ++kk) {
            const uint32_t ko = kk * 32;
            uint32_t ah[2][4], al[2][4], bh[8][2], bl[8][2];
            #pragma unroll
            for (int mt = 0; mt < 2; ++mt) {
                const uint32_t ba = stg + aRowB + mt * 16 * (PITCH * 2) + ko;
                ah[mt][0] = lds32(ba);
                ah[mt][1] = lds32(ba + 8 * (PITCH * 2));
                ah[mt][2] = lds32(ba + 16);
                ah[mt][3] = lds32(ba + 8 * (PITCH * 2) + 16);
                const uint32_t bal = ba + ARR_BYTES;
                al[mt][0] = lds32(bal);
                al[mt][1] = lds32(bal + 8 * (PITCH * 2));
                al[mt][2] = lds32(bal + 16);
                al[mt][3] = lds32(bal + 8 * (PITCH * 2) + 16);
            }
            #pragma unroll
            for (int nt = 0; nt < 8; ++nt) {
                const uint32_t bb = stg + 2 * ARR_BYTES + bColB + nt * 8 * (PITCH * 2) + ko;
                bh[nt][0] = lds32(bb);
                bh[nt][1] = lds32(bb + 16);
                bl[nt][0] = lds32(bb + ARR_BYTES);
                bl[nt][1] = lds32(bb + ARR_BYTES + 16);
            }
            #pragma unroll
            for (int mt = 0; mt < 2; ++mt)
                #pragma unroll
                for (int nt = 0; nt < 8; ++nt)
                    mma16816(acc[mt][nt], ah[mt], bh[nt]);
            #pragma unroll
            for (int mt = 0; mt < 2; ++mt)
                #pragma unroll
                for (int nt = 0; nt < 8; ++nt)
                    mma16816(acc[mt][nt], ah[mt], bl[nt]);
            #pragma unroll
            for (int mt = 0; mt < 2; ++mt)
                #pragma unroll
                for (int nt = 0; nt < 8; ++nt)
                    mma16816(acc[mt][nt], al[mt], bh[nt]);
        }
        __syncthreads();
    }

    // Epilogue: bias add, split, scatter
    #pragma unroll
    for (int mt = 0; mt < 2; ++mt) {
        const int row0 = rowBase + wm * 32 + mt * 16 + g;
        #pragma unroll
        for (int nt = 0; nt < 8; ++nt) {
            const int col = colBase + wn * 64 + nt * 8 + 2 * c;
            const float bx = __ldg(&bias[col]);
            const float by = __ldg(&bias[col + 1]);
            const int h = col >> 6, hd = col & 63;
            #pragma unroll
            for (int half = 0; half < 2; ++half) {
                const int row = row0 + half * 8;
                const int b = row >> 11, s = row & 2047;
                const float vx = acc[mt][nt][half * 2 + 0] + bx;
                const float vy = acc[mt][nt][half * 2 + 1] + by;
                if (which < 2) {
                    const __nv_bfloat16 hx = __float2bfloat16(vx);
                    const __nv_bfloat16 hy = __float2bfloat16(vy);
                    const __nv_bfloat16 lx = __float2bfloat16(vx - __bfloat162float(hx));
                    const __nv_bfloat16 ly = __float2bfloat16(vy - __bfloat162float(hy));
                    const size_t o = (((size_t)b * NHEAD + h) * SEQ + s) * HDIM + hd;
                    *(__nv_bfloat162*)&oh[o] = __halves2bfloat162(hx, hy);
                    *(__nv_bfloat162*)&ol[o] = __halves2bfloat162(lx, ly);
                } else {
                    // V: fp16 hi/lo, transposed [B,H,HD,L]
                    const __half hx = __float2half(vx);
                    const __half hy = __float2half(vy);
                    const __half lx = __float2half(vx - __half2float(hx));
                    const __half ly = __float2half(vy - __half2float(hy));
                    const size_t o = (((size_t)b * NHEAD + h) * HDIM + hd) * SEQ + s;
                    g_Vthi[o] = hx; g_Vthi[o + SEQ] = hy;
                    g_Vtlo[o] = lx; g_Vtlo[o + SEQ] = ly;
                }
            }
        }
    }
}

// ---------------------------------------------------------------------------
// Tensor-core flash attention (causal). CTA = 64 q-rows, 4 warps (m16 each).
// S: bf16 3-term.  P·V: fp16 2-term (P single fp16, V fp16 hi/lo).
// ---------------------------------------------------------------------------
#define AP2 144
#define TILEB (64 * AP2)
#define KHI_O 0
#define KLO_O TILEB
#define VHI_O (2 * TILEB)
#define VLO_O (3 * TILEB)
#define ASTGB (4 * TILEB)
#define ATT_SMEM (2 * ASTGB)

__device__ __forceinline__ void load_kv_tile(uint32_t stg, int bh, int key0, int tid)
{
    const __nv_bfloat16* kh = g_Khi + ((size_t)bh * SEQ + key0) * HDIM;
    const __nv_bfloat16* kl = g_Klo + ((size_t)bh * SEQ + key0) * HDIM;
    const __half* vh = g_Vthi + (size_t)bh * HDIM * SEQ + key0;
    const __half* vl = g_Vtlo + (size_t)bh * HDIM * SEQ + key0;
    #pragma unroll
    for (int it = 0; it < 4; ++it) {
        const int u = tid + it * 128;
        const int r = u >> 3, cc = u & 7;
        cp16(stg + KHI_O + r * AP2 + cc * 16, kh + r * HDIM + cc * 8);
        cp16(stg + KLO_O + r * AP2 + cc * 16, kl + r * HDIM + cc * 8);
        cp16(stg + VHI_O + r * AP2 + cc * 16, vh + (size_t)r * SEQ + cc * 8);
        cp16(stg + VLO_O + r * AP2 + cc * 16, vl + (size_t)r * SEQ + cc * 8);
    }
}

__global__ __launch_bounds__(128) void attn_kernel(float* __restrict__ out)
{
    extern __shared__ char smemc[];
    const uint32_t sb = smem_u32(smemc);
    const int tid = threadIdx.x;
    const int warp = tid >> 5;
    const int lane = tid & 31;
    const int g = lane >> 2;
    const int c = lane & 3;
    const int moff = warp * 16;

    const int bh = blockIdx.y;
    const int b = bh >> 4;
    const int h = bh & 15;
    const int qi = (SEQ / 64 - 1) - blockIdx.x;

    {
        const __nv_bfloat16* qh = g_Qhi + ((size_t)bh * SEQ + (size_t)qi * 64) * HDIM;
        const __nv_bfloat16* ql = g_Qlo + ((size_t)bh * SEQ + (size_t)qi * 64) * HDIM;
        #pragma unroll
        for (int it = 0; it < 4; ++it) {
            const int u = tid + it * 128;
            const int r = u >> 3, cc = u & 7;
            cp16(sb + ASTGB + KHI_O + r * AP2 + cc * 16, qh + r * HDIM + cc * 8);
            cp16(sb + ASTGB + KLO_O + r * AP2 + cc * 16, ql + r * HDIM + cc * 8);
        }
        CP_COMMIT();
        load_kv_tile(sb, bh, 0, tid);
        CP_COMMIT();
    }

    uint32_t qhi[4][4], qlo[4][4];
    CP_WAIT(1);
    __syncthreads();
    {
        const uint32_t qb = sb + ASTGB + KHI_O + (uint32_t)(moff + g) * AP2 + c * 4;
        #pragma unroll
        for (int kt = 0; kt < 4; ++kt) {
            qhi[kt][0] = lds32(qb + kt * 32);
            qhi[kt][1] = lds32(qb + kt * 32 + 8 * AP2);
            qhi[kt][2] = lds32(qb + kt * 32 + 16);
            qhi[kt][3] = lds32(qb + kt * 32 + 8 * AP2 + 16);
            qlo[kt][0] = lds32(qb + TILEB + kt * 32);
            qlo[kt][1] = lds32(qb + TILEB + kt * 32 + 8 * AP2);
            qlo[kt][2] = lds32(qb + TILEB + kt * 32 + 16);
            qlo[kt][3] = lds32(qb + TILEB + kt * 32 + 8 * AP2 + 16);
        }
    }
    __syncthreads();

    float O[8][4] = {};
    float m[2] = {-1e30f, -1e30f};
    float l[2] = {0.0f, 0.0f};

    for (int jb = 0; jb <= qi; ++jb) {
        const uint32_t stg = sb + (uint32_t)(jb & 1) * ASTGB;
        if (jb < qi) {
            load_kv_tile(sb + (uint32_t)((jb + 1) & 1) * ASTGB, bh, (jb + 1) * 64, tid);
            CP_COMMIT();
            CP_WAIT(1);
        } else {
            CP_WAIT(0);
        }
        __syncthreads();

        // ----- S = Q K^T (bf16 3-term) -----
        float S[8][4] = {};
        #pragma unroll
        for (int kt = 0; kt < 4; ++kt) {
            uint32_t bhf[8][2], blf[8][2];
            const uint32_t kb = stg + KHI_O + (uint32_t)g * AP2 + kt * 32 + c * 4;
            #pragma unroll
            for (int nt = 0; nt < 8; ++nt) {
                const uint32_t a0 = kb + nt * 8 * AP2;
                bhf[nt][0] = lds32(a0);
                bhf[nt][1] = lds32(a0 + 16);
                blf[nt][0] = lds32(a0 + TILEB);
                blf[nt][1] = lds32(a0 + TILEB + 16);
            }
            #pragma unroll
            for (int nt = 0; nt < 8; ++nt) mma16816(S[nt], qhi[kt], bhf[nt]);
            #pragma unroll
            for (int nt = 0; nt < 8; ++nt) mma16816(S[nt], qhi[kt], blf[nt]);
            #pragma unroll
            for (int nt = 0; nt < 8; ++nt) mma16816(S[nt], qlo[kt], bhf[nt]);
        }

        // ----- scale + causal mask -----
        const bool diag = (jb == qi);
        #pragma unroll
        for (int nt = 0; nt < 8; ++nt) {
            #pragma unroll
            for (int e = 0; e < 4; ++e) {
                float v = S[nt][e] * SCALE;
                if (diag) {
                    const int col = nt * 8 + 2 * c + (e & 1);
                    const int row = moff + g + ((e >> 1) << 3);
                    if (col > row) v = -1e30f;
                }
                S[nt][e] = v;
            }
        }

        // ----- online softmax -----
        float rowm[2] = {-1e30f, -1e30f};
        #pragma unroll
        for (int nt = 0; nt < 8; ++nt) {
            rowm[0] = fmaxf(rowm[0], fmaxf(S[nt][0], S[nt][1]));
            rowm[1] = fmaxf(rowm[1], fmaxf(S[nt][2], S[nt][3]));
        }
        #pragma unroll
        for (int r = 0; r < 2; ++r) {
            rowm[r] = fmaxf(rowm[r], __shfl_xor_sync(0xffffffffu, rowm[r], 1));
            rowm[r] = fmaxf(rowm[r], __shfl_xor_sync(0xffffffffu, rowm[r], 2));
        }
        float corr[2];
        #pragma unroll
        for (int r = 0; r < 2; ++r) {
            const float mnew = fmaxf(m[r], rowm[r]);
            corr[r] = fexp(m[r] - mnew);
            l[r] *= corr[r];
            m[r] = mnew;
        }
        #pragma unroll
        for (int nt = 0; nt < 8; ++nt) {
            O[nt][0] *= corr[0]; O[nt][1] *= corr[0];
            O[nt][2] *= corr[1]; O[nt][3] *= corr[1];
        }
        float psum[2] = {0.0f, 0.0f};
        #pragma unroll
        for (int nt = 0; nt < 8; ++nt) {
            #pragma unroll
            for (int e = 0; e < 4; ++e) {
                const float p = fexp(S[nt][e] - m[e >> 1]);
                S[nt][e] = p;
                psum[e >> 1] += p;
            }
        }
        #pragma unroll
        for (int r = 0; r < 2; ++r) {
            psum[r] += __shfl_xor_sync(0xffffffffu, psum[r], 1);
            psum[r] += __shfl_xor_sync(0xffffffffu, psum[r], 2);
            l[r] += psum[r];
        }

        // ----- P -> single fp16 A-fragments -----
        uint32_t pfp[4][4];
        #pragma unroll
        for (int t = 0; t < 8; ++t) {
            const int kt = t >> 1;
            const int sl = (t & 1) << 1;
            pfp[kt][sl + 0] = pack_h2(S[t][0], S[t][1]);
            pfp[kt][sl + 1] = pack_h2(S[t][2], S[t][3]);
        }

        // ----- O += P V (fp16 2-term) -----
        #pragma unroll
        for (int kt = 0; kt < 4; ++kt) {
            uint32_t vhf[8][2], vlf[8][2];
            const uint32_t vb = stg + VHI_O + (uint32_t)g * AP2 + kt * 32 + c * 4;
            #pragma unroll
            for (int nt = 0; nt < 8; ++nt) {
                const uint32_t a0 = vb + nt * 8 * AP2;
                vhf[nt][0] = lds32(a0);
                vhf[nt][1] = lds32(a0 + 16);
                vlf[nt][0] = lds32(a0 + TILEB);
                vlf[nt][1] = lds32(a0 + TILEB + 16);
            }
            #pragma unroll
            for (int nt = 0; nt < 8; ++nt) mma16816h(O[nt], pfp[kt], vhf[nt][0], vhf[nt][1]);
            #pragma unroll
            for (int nt = 0; nt < 8; ++nt) mma16816h(O[nt], pfp[kt], vlf[nt][0], vlf[nt][1]);
        }
        __syncthreads();
    }

    const float inv0 = 1.0f / l[0];
    const float inv1 = 1.0f / l[1];
    const int row0 = qi * 64 + moff + g;
    #pragma unroll
    for (int nt = 0; nt < 8; ++nt) {
        const int col = h * HDIM + nt * 8 + 2 * c;
        float2 v0 = {O[nt][0] * inv0, O[nt][1] * inv0};
        float2 v1 = {O[nt][2] * inv1, O[nt][3] * inv1};
        *(float2*)&out[((size_t)b * SEQ + row0) * DMODEL + col] = v0;
        *(float2*)&out[((size_t)b * SEQ + row0 + 8) * DMODEL + col] = v1;
    }
}

// ---------------------------------------------------------------------------
extern "C" void kernel_launch(void* const* d_in, const int* in_sizes, int n_in,
                              void* d_out, int out_size)
{
    const float* X  = (const float*)d_in[0];
    const float* Wq = (const float*)d_in[1];
    const float* bq = (const float*)d_in[2];
    const float* Wk = (const float*)d_in[3];
    const float* bk = (const float*)d_in[4];
    const float* Wv = (const float*)d_in[5];
    const float* bv = (const float*)d_in[6];
    float* out = (float*)d_out;

    __nv_bfloat16 *xhi, *xlo, *whi, *wlo;
    cudaGetSymbolAddress((void**)&xhi, g_Xhi);
    cudaGetSymbolAddress((void**)&xlo, g_Xlo);
    cudaGetSymbolAddress((void**)&whi, g_Whi);
    cudaGetSymbolAddress((void**)&wlo, g_Wlo);

    const int xN4 = BATCH * SEQ * DMODEL / 4;
    const int wN4 = DMODEL * DMODEL / 4;
    split_kernel<<<xN4 / 256, 256>>>(X, xhi, xlo);
    split_kernel<<<wN4 / 256, 256>>>(Wq, whi + 0 * (size_t)DMODEL * DMODEL,
                                         wlo + 0 * (size_t)DMODEL * DMODEL);
    split_kernel<<<wN4 / 256, 256>>>(Wk, whi + 1 * (size_t)DMODEL * DMODEL,
                                         wlo + 1 * (size_t)DMODEL * DMODEL);
    split_kernel<<<wN4 / 256, 256>>>(Wv, whi + 2 * (size_t)DMODEL * DMODEL,
                                         wlo + 2 * (size_t)DMODEL * DMODEL);

    cudaFuncSetAttribute(gemm_kernel, cudaFuncAttributeMaxDynamicSharedMemorySize,
                         GEMM_SMEM);
    dim3 gg((BATCH * SEQ) / 128, DMODEL / 128, 3);
    gemm_kernel<<<gg, 256, GEMM_SMEM>>>(bq, bk, bv);

    cudaFuncSetAttribute(attn_kernel, cudaFuncAttributeMaxDynamicSharedMemorySize,
                         ATT_SMEM);
    dim3 ag(SEQ / 64, BATCH * NHEAD);
    attn_kernel<<<ag, 128, ATT_SMEM>>>(out);
}

// round 11
// speedup vs baseline: 4.1194x; 1.3108x over previous
#include <cuda_runtime.h>
#include <cuda_bf16.h>
#include <cuda_fp16.h>
#include <cstdint>

// Problem constants
#define BATCH 4
#define SEQ   2048
#define DMODEL 1024
#define NHEAD 16
#define HDIM  64
#define SCALE 0.25f

// ---------------------------------------------------------------------------
// Static device scratch (all fp16 now)
// ---------------------------------------------------------------------------
#define QKV_ELEMS ((size_t)BATCH * NHEAD * SEQ * HDIM)
__device__ __half g_Qh[QKV_ELEMS];
__device__ __half g_Ql[QKV_ELEMS];
__device__ __half g_Kh[QKV_ELEMS];
__device__ __half g_Kl[QKV_ELEMS];
__device__ __half g_Vt[QKV_ELEMS];            // [B,H,HD,L] transposed, single fp16

__device__ __half g_Xh[(size_t)BATCH * SEQ * DMODEL];    // X truncated to fp16
__device__ __half g_Wh[(size_t)3 * DMODEL * DMODEL];     // W fp16 hi
__device__ __half g_Wl[(size_t)3 * DMODEL * DMODEL];     // W fp16 lo

// ---------------------------------------------------------------------------
// Helpers
// ---------------------------------------------------------------------------
__device__ __forceinline__ uint32_t smem_u32(const void* p) {
    uint32_t a;
    asm("{ .reg .u64 t; cvta.to.shared.u64 t, %1; cvt.u32.u64 %0, t; }"
        : "=r"(a) : "l"(p));
    return a;
}

__device__ __forceinline__ void cp16(uint32_t d, const void* s) {
    asm volatile("cp.async.cg.shared.global [%0], [%1], 16;" :: "r"(d), "l"(s) : "memory");
}
#define CP_COMMIT() asm volatile("cp.async.commit_group;" ::: "memory")
#define CP_WAIT(N)  asm volatile("cp.async.wait_group %0;" :: "n"(N) : "memory")

__device__ __forceinline__ uint32_t lds32(uint32_t a) {
    uint32_t v;
    asm volatile("ld.shared.b32 %0, [%1];" : "=r"(v) : "r"(a));
    return v;
}

// fp16 mma: m16n8k16 -> f32
__device__ __forceinline__ void mma16816h(float* c, const uint32_t* a,
                                          uint32_t b0, uint32_t b1) {
    asm volatile(
        "mma.sync.aligned.m16n8k16.row.col.f32.f16.f16.f32 "
        "{%0,%1,%2,%3}, {%4,%5,%6,%7}, {%8,%9}, {%0,%1,%2,%3};"
        : "+f"(c[0]), "+f"(c[1]), "+f"(c[2]), "+f"(c[3])
        : "r"(a[0]), "r"(a[1]), "r"(a[2]), "r"(a[3]), "r"(b0), "r"(b1));
}

// Fast exp on the FMA pipe (x <= 0), rel err ~1e-5.
__device__ __forceinline__ float fexp(float x) {
    x = fmaxf(x, -87.0f);
    const float y = x * 1.44269504f;
    const float fl = floorf(y);
    const float f = y - fl;
    float p = 1.5403530e-4f;
    p = fmaf(p, f, 1.3333558e-3f);
    p = fmaf(p, f, 9.6181291e-3f);
    p = fmaf(p, f, 5.5504109e-2f);
    p = fmaf(p, f, 2.4022651e-1f);
    p = fmaf(p, f, 6.9314718e-1f);
    p = fmaf(p, f, 1.0f);
    return __int_as_float(__float_as_int(p) + (((int)fl) << 23));
}

__device__ __forceinline__ uint32_t pack_h2(float x, float y) {
    __half2 t = __halves2half2(__float2half(x), __float2half(y));
    return *(uint32_t*)&t;
}

// ---------------------------------------------------------------------------
// Split fp32 -> fp16 hi (+ optional lo)
// ---------------------------------------------------------------------------
__global__ __launch_bounds__(256) void split16_kernel(
    const float* __restrict__ src,
    __half* __restrict__ hi, __half* __restrict__ lo)
{
    const int i = blockIdx.x * 256 + threadIdx.x;
    float4 v = ((const float4*)src)[i];
    float a[4] = {v.x, v.y, v.z, v.w};
    __half h[4], l[4];
    #pragma unroll
    for (int j = 0; j < 4; ++j) {
        h[j] = __float2half(a[j]);
        l[j] = __float2half(a[j] - __half2float(h[j]));
    }
    ((__half2*)hi)[2 * i + 0] = __halves2half2(h[0], h[1]);
    ((__half2*)hi)[2 * i + 1] = __halves2half2(h[2], h[3]);
    if (lo) {
        ((__half2*)lo)[2 * i + 0] = __halves2half2(l[0], l[1]);
        ((__half2*)lo)[2 * i + 1] = __halves2half2(l[2], l[3]);
    }
}

// ---------------------------------------------------------------------------
// fp16 2-term projection GEMM: C = X16 @ (Wh + Wl)^T + bias.
// CTA 128x128, 8 warps (4x2), warp tile 32x64, kc=32 double-buffered cp.async.
// Smem arrays: Ah, Bh, Bl (pitch 40 fp16 = 80B, conflict-free fragment LDS).
// Epilogue: Q,K fp16 hi/lo [B,H,L,HD]; V single fp16 transposed [B,H,HD,L].
// ---------------------------------------------------------------------------
#define PITCH 40
#define ARR_BYTES (128 * PITCH * 2)      // 10240
#define STG_BYTES (3 * ARR_BYTES)        // 30720 (Ah, Bh, Bl)
#define GEMM_SMEM (2 * STG_BYTES)        // 61440

__device__ __forceinline__ void load_stage(
    uint32_t stg, const __half* __restrict__ Xh,
    const __half* __restrict__ Wh, const __half* __restrict__ Wl,
    int rowBase, int colBase, int k0, int tid)
{
    #pragma unroll
    for (int it = 0; it < 6; ++it) {
        const int u = tid + it * 256;          // 0..1535
        const int arr = u >> 9;                // 0:Ah 1:Bh 2:Bl
        const int r = (u >> 2) & 127;
        const int cc = u & 3;
        const __half* src;
        if (arr == 0)      src = Xh + (size_t)(rowBase + r) * DMODEL + k0 + cc * 8;
        else if (arr == 1) src = Wh + (size_t)(colBase + r) * DMODEL + k0 + cc * 8;
        else               src = Wl + (size_t)(colBase + r) * DMODEL + k0 + cc * 8;
        cp16(stg + arr * ARR_BYTES + r * (PITCH * 2) + cc * 16, src);
    }
}

__global__ __launch_bounds__(256) void gemm_kernel(
    const float* __restrict__ bq, const float* __restrict__ bk,
    const float* __restrict__ bv)
{
    extern __shared__ char smem[];
    const uint32_t sb = smem_u32(smem);
    const int tid = threadIdx.x;
    const int warp = tid >> 5;
    const int lane = tid & 31;
    const int g = lane >> 2;
    const int c = lane & 3;
    const int wm = warp >> 1;
    const int wn = warp & 1;

    const int which = blockIdx.z;
    const __half* Wh = g_Wh + (size_t)which * DMODEL * DMODEL;
    const __half* Wl = g_Wl + (size_t)which * DMODEL * DMODEL;
    const float* bias = (which == 0) ? bq : (which == 1) ? bk : bv;
    __half* oh = (which == 0) ? g_Qh : g_Kh;
    __half* ol = (which == 0) ? g_Ql : g_Kl;

    const int rowBase = blockIdx.x * 128;
    const int colBase = blockIdx.y * 128;

    float acc[2][8][4] = {};

    load_stage(sb, g_Xh, Wh, Wl, rowBase, colBase, 0, tid);
    CP_COMMIT();

    const uint32_t aRowB = (uint32_t)(wm * 32 + g) * (PITCH * 2) + c * 4;
    const uint32_t bColB = (uint32_t)(wn * 64 + g) * (PITCH * 2) + c * 4;

    for (int sidx = 0; sidx < DMODEL / 32; ++sidx) {
        const uint32_t stg = sb + (uint32_t)(sidx & 1) * STG_BYTES;
        if (sidx + 1 < DMODEL / 32) {
            load_stage(sb + (uint32_t)((sidx + 1) & 1) * STG_BYTES,
                       g_Xh, Wh, Wl, rowBase, colBase, (sidx + 1) * 32, tid);
            CP_COMMIT();
            CP_WAIT(1);
        } else {
            CP_WAIT(0);
        }
        __syncthreads();

        #pragma unroll
        for (int kk = 0; kk < 2; ++kk) {
            const uint32_t ko = kk * 32;
            uint32_t ah[2][4], bh[8][2], bl[8][2];
            #pragma unroll
            for (int mt = 0; mt < 2; ++mt) {
                const uint32_t ba = stg + aRowB + mt * 16 * (PITCH * 2) + ko;
                ah[mt][0] = lds32(ba);
                ah[mt][1] = lds32(ba + 8 * (PITCH * 2));
                ah[mt][2] = lds32(ba + 16);
                ah[mt][3] = lds32(ba + 8 * (PITCH * 2) + 16);
            }
            #pragma unroll
            for (int nt = 0; nt < 8; ++nt) {
                const uint32_t bb = stg + ARR_BYTES + bColB + nt * 8 * (PITCH * 2) + ko;
                bh[nt][0] = lds32(bb);
                bh[nt][1] = lds32(bb + 16);
                bl[nt][0] = lds32(bb + ARR_BYTES);
                bl[nt][1] = lds32(bb + ARR_BYTES + 16);
            }
            #pragma unroll
            for (int mt = 0; mt < 2; ++mt)
                #pragma unroll
                for (int nt = 0; nt < 8; ++nt)
                    mma16816h(acc[mt][nt], ah[mt], bh[nt][0], bh[nt][1]);
            #pragma unroll
            for (int mt = 0; mt < 2; ++mt)
                #pragma unroll
                for (int nt = 0; nt < 8; ++nt)
                    mma16816h(acc[mt][nt], ah[mt], bl[nt][0], bl[nt][1]);
        }
        __syncthreads();
    }

    // Epilogue
    #pragma unroll
    for (int mt = 0; mt < 2; ++mt) {
        const int row0 = rowBase + wm * 32 + mt * 16 + g;
        #pragma unroll
        for (int nt = 0; nt < 8; ++nt) {
            const int col = colBase + wn * 64 + nt * 8 + 2 * c;
            const float bx = __ldg(&bias[col]);
            const float by = __ldg(&bias[col + 1]);
            const int h = col >> 6, hd = col & 63;
            #pragma unroll
            for (int half = 0; half < 2; ++half) {
                const int row = row0 + half * 8;
                const int b = row >> 11, s = row & 2047;
                const float vx = acc[mt][nt][half * 2 + 0] + bx;
                const float vy = acc[mt][nt][half * 2 + 1] + by;
                if (which < 2) {
                    const __half hx = __float2half(vx);
                    const __half hy = __float2half(vy);
                    const __half lx = __float2half(vx - __half2float(hx));
                    const __half ly = __float2half(vy - __half2float(hy));
                    const size_t o = (((size_t)b * NHEAD + h) * SEQ + s) * HDIM + hd;
                    *(__half2*)&oh[o] = __halves2half2(hx, hy);
                    *(__half2*)&ol[o] = __halves2half2(lx, ly);
                } else {
                    const size_t o = (((size_t)b * NHEAD + h) * HDIM + hd) * SEQ + s;
                    g_Vt[o] = __float2half(vx);
                    g_Vt[o + SEQ] = __float2half(vy);
                }
            }
        }
    }
}

// ---------------------------------------------------------------------------
// Tensor-core flash attention (causal). CTA = 64 q-rows, 4 warps (m16 each).
// S: fp16 3-term (Qh·Kh + Qh·Kl + Ql·Kh). P·V: fp16 1-term (P fp16, V fp16).
// ---------------------------------------------------------------------------
#define AP2 144
#define TILEB (64 * AP2)
#define KH_O 0
#define KL_O TILEB
#define V_O  (2 * TILEB)
#define ASTGB (3 * TILEB)       // 27648 per stage
#define ATT_SMEM (2 * ASTGB)    // 55296

__device__ __forceinline__ void load_kv_tile(uint32_t stg, int bh, int key0, int tid)
{
    const __half* kh = g_Kh + ((size_t)bh * SEQ + key0) * HDIM;
    const __half* kl = g_Kl + ((size_t)bh * SEQ + key0) * HDIM;
    const __half* vt = g_Vt + (size_t)bh * HDIM * SEQ + key0;
    #pragma unroll
    for (int it = 0; it < 4; ++it) {
        const int u = tid + it * 128;
        const int r = u >> 3, cc = u & 7;
        cp16(stg + KH_O + r * AP2 + cc * 16, kh + r * HDIM + cc * 8);
        cp16(stg + KL_O + r * AP2 + cc * 16, kl + r * HDIM + cc * 8);
        cp16(stg + V_O  + r * AP2 + cc * 16, vt + (size_t)r * SEQ + cc * 8);
    }
}

__global__ __launch_bounds__(128) void attn_kernel(float* __restrict__ out)
{
    extern __shared__ char smemc[];
    const uint32_t sb = smem_u32(smemc);
    const int tid = threadIdx.x;
    const int warp = tid >> 5;
    const int lane = tid & 31;
    const int g = lane >> 2;
    const int c = lane & 3;
    const int moff = warp * 16;

    const int bh = blockIdx.y;
    const int b = bh >> 4;
    const int h = bh & 15;
    const int qi = (SEQ / 64 - 1) - blockIdx.x;   // heavy q-tiles first

    // Stage Q hi/lo into stage-1 K slots; K/V tile 0 into stage 0
    {
        const __half* qh = g_Qh + ((size_t)bh * SEQ + (size_t)qi * 64) * HDIM;
        const __half* ql = g_Ql + ((size_t)bh * SEQ + (size_t)qi * 64) * HDIM;
        #pragma unroll
        for (int it = 0; it < 4; ++it) {
            const int u = tid + it * 128;
            const int r = u >> 3, cc = u & 7;
            cp16(sb + ASTGB + KH_O + r * AP2 + cc * 16, qh + r * HDIM + cc * 8);
            cp16(sb + ASTGB + KL_O + r * AP2 + cc * 16, ql + r * HDIM + cc * 8);
        }
        CP_COMMIT();
        load_kv_tile(sb, bh, 0, tid);
        CP_COMMIT();
    }

    uint32_t qhf[4][4], qlf[4][4];
    CP_WAIT(1);
    __syncthreads();
    {
        const uint32_t qb = sb + ASTGB + KH_O + (uint32_t)(moff + g) * AP2 + c * 4;
        #pragma unroll
        for (int kt = 0; kt < 4; ++kt) {
            qhf[kt][0] = lds32(qb + kt * 32);
            qhf[kt][1] = lds32(qb + kt * 32 + 8 * AP2);
            qhf[kt][2] = lds32(qb + kt * 32 + 16);
            qhf[kt][3] = lds32(qb + kt * 32 + 8 * AP2 + 16);
            qlf[kt][0] = lds32(qb + TILEB + kt * 32);
            qlf[kt][1] = lds32(qb + TILEB + kt * 32 + 8 * AP2);
            qlf[kt][2] = lds32(qb + TILEB + kt * 32 + 16);
            qlf[kt][3] = lds32(qb + TILEB + kt * 32 + 8 * AP2 + 16);
        }
    }
    __syncthreads();

    float O[8][4] = {};
    float m[2] = {-1e30f, -1e30f};
    float l[2] = {0.0f, 0.0f};

    for (int jb = 0; jb <= qi; ++jb) {
        const uint32_t stg = sb + (uint32_t)(jb & 1) * ASTGB;
        if (jb < qi) {
            load_kv_tile(sb + (uint32_t)((jb + 1) & 1) * ASTGB, bh, (jb + 1) * 64, tid);
            CP_COMMIT();
            CP_WAIT(1);
        } else {
            CP_WAIT(0);
        }
        __syncthreads();

        // ----- S = Q K^T (fp16 3-term) -----
        float S[8][4] = {};
        #pragma unroll
        for (int kt = 0; kt < 4; ++kt) {
            uint32_t bhf[8][2], blf[8][2];
            const uint32_t kb = stg + KH_O + (uint32_t)g * AP2 + kt * 32 + c * 4;
            #pragma unroll
            for (int nt = 0; nt < 8; ++nt) {
                const uint32_t a0 = kb + nt * 8 * AP2;
                bhf[nt][0] = lds32(a0);
                bhf[nt][1] = lds32(a0 + 16);
                blf[nt][0] = lds32(a0 + TILEB);
                blf[nt][1] = lds32(a0 + TILEB + 16);
            }
            #pragma unroll
            for (int nt = 0; nt < 8; ++nt) mma16816h(S[nt], qhf[kt], bhf[nt][0], bhf[nt][1]);
            #pragma unroll
            for (int nt = 0; nt < 8; ++nt) mma16816h(S[nt], qhf[kt], blf[nt][0], blf[nt][1]);
            #pragma unroll
            for (int nt = 0; nt < 8; ++nt) mma16816h(S[nt], qlf[kt], bhf[nt][0], bhf[nt][1]);
        }

        // ----- scale + causal mask -----
        const bool diag = (jb == qi);
        #pragma unroll
        for (int nt = 0; nt < 8; ++nt) {
            #pragma unroll
            for (int e = 0; e < 4; ++e) {
                float v = S[nt][e] * SCALE;
                if (diag) {
                    const int col = nt * 8 + 2 * c + (e & 1);
                    const int row = moff + g + ((e >> 1) << 3);
                    if (col > row) v = -1e30f;
                }
                S[nt][e] = v;
            }
        }

        // ----- online softmax -----
        float rowm[2] = {-1e30f, -1e30f};
        #pragma unroll
        for (int nt = 0; nt < 8; ++nt) {
            rowm[0] = fmaxf(rowm[0], fmaxf(S[nt][0], S[nt][1]));
            rowm[1] = fmaxf(rowm[1], fmaxf(S[nt][2], S[nt][3]));
        }
        #pragma unroll
        for (int r = 0; r < 2; ++r) {
            rowm[r] = fmaxf(rowm[r], __shfl_xor_sync(0xffffffffu, rowm[r], 1));
            rowm[r] = fmaxf(rowm[r], __shfl_xor_sync(0xffffffffu, rowm[r], 2));
        }
        float corr[2];
        #pragma unroll
        for (int r = 0; r < 2; ++r) {
            const float mnew = fmaxf(m[r], rowm[r]);
            corr[r] = fexp(m[r] - mnew);
            l[r] *= corr[r];
            m[r] = mnew;
        }
        #pragma unroll
        for (int nt = 0; nt < 8; ++nt) {
            O[nt][0] *= corr[0]; O[nt][1] *= corr[0];
            O[nt][2] *= corr[1]; O[nt][3] *= corr[1];
        }
        float psum[2] = {0.0f, 0.0f};
        #pragma unroll
        for (int nt = 0; nt < 8; ++nt) {
            #pragma unroll
            for (int e = 0; e < 4; ++e) {
                const float p = fexp(S[nt][e] - m[e >> 1]);
                S[nt][e] = p;
                psum[e >> 1] += p;
            }
        }
        #pragma unroll
        for (int r = 0; r < 2; ++r) {
            psum[r] += __shfl_xor_sync(0xffffffffu, psum[r], 1);
            psum[r] += __shfl_xor_sync(0xffffffffu, psum[r], 2);
            l[r] += psum[r];
        }

        // ----- P -> single fp16 A-fragments -----
        uint32_t pfp[4][4];
        #pragma unroll
        for (int t = 0; t < 8; ++t) {
            const int kt = t >> 1;
            const int sl = (t & 1) << 1;
            pfp[kt][sl + 0] = pack_h2(S[t][0], S[t][1]);
            pfp[kt][sl + 1] = pack_h2(S[t][2], S[t][3]);
        }

        // ----- O += P V (fp16 1-term) -----
        #pragma unroll
        for (int kt = 0; kt < 4; ++kt) {
            uint32_t vhf[8][2];
            const uint32_t vb = stg + V_O + (uint32_t)g * AP2 + kt * 32 + c * 4;
            #pragma unroll
            for (int nt = 0; nt < 8; ++nt) {
                const uint32_t a0 = vb + nt * 8 * AP2;
                vhf[nt][0] = lds32(a0);
                vhf[nt][1] = lds32(a0 + 16);
            }
            #pragma unroll
            for (int nt = 0; nt < 8; ++nt) mma16816h(O[nt], pfp[kt], vhf[nt][0], vhf[nt][1]);
        }
        __syncthreads();
    }

    const float inv0 = 1.0f / l[0];
    const float inv1 = 1.0f / l[1];
    const int row0 = qi * 64 + moff + g;
    #pragma unroll
    for (int nt = 0; nt < 8; ++nt) {
        const int col = h * HDIM + nt * 8 + 2 * c;
        float2 v0 = {O[nt][0] * inv0, O[nt][1] * inv0};
        float2 v1 = {O[nt][2] * inv1, O[nt][3] * inv1};
        *(float2*)&out[((size_t)b * SEQ + row0) * DMODEL + col] = v0;
        *(float2*)&out[((size_t)b * SEQ + row0 + 8) * DMODEL + col] = v1;
    }
}

// ---------------------------------------------------------------------------
extern "C" void kernel_launch(void* const* d_in, const int* in_sizes, int n_in,
                              void* d_out, int out_size)
{
    const float* X  = (const float*)d_in[0];
    const float* Wq = (const float*)d_in[1];
    const float* bq = (const float*)d_in[2];
    const float* Wk = (const float*)d_in[3];
    const float* bk = (const float*)d_in[4];
    const float* Wv = (const float*)d_in[5];
    const float* bv = (const float*)d_in[6];
    float* out = (float*)d_out;

    __half *xh, *wh, *wl;
    cudaGetSymbolAddress((void**)&xh, g_Xh);
    cudaGetSymbolAddress((void**)&wh, g_Wh);
    cudaGetSymbolAddress((void**)&wl, g_Wl);

    const int xN4 = BATCH * SEQ * DMODEL / 4;
    const int wN4 = DMODEL * DMODEL / 4;
    const size_t wsz = (size_t)DMODEL * DMODEL;
    split16_kernel<<<xN4 / 256, 256>>>(X, xh, (__half*)nullptr);
    split16_kernel<<<wN4 / 256, 256>>>(Wq, wh + 0 * wsz, wl + 0 * wsz);
    split16_kernel<<<wN4 / 256, 256>>>(Wk, wh + 1 * wsz, wl + 1 * wsz);
    split16_kernel<<<wN4 / 256, 256>>>(Wv, wh + 2 * wsz, wl + 2 * wsz);

    cudaFuncSetAttribute(gemm_kernel, cudaFuncAttributeMaxDynamicSharedMemorySize,
                         GEMM_SMEM);
    dim3 gg((BATCH * SEQ) / 128, DMODEL / 128, 3);
    gemm_kernel<<<gg, 256, GEMM_SMEM>>>(bq, bk, bv);

    cudaFuncSetAttribute(attn_kernel, cudaFuncAttributeMaxDynamicSharedMemorySize,
                         ATT_SMEM);
    dim3 ag(SEQ / 64, BATCH * NHEAD);
    attn_kernel<<<ag, 128, ATT_SMEM>>>(out);
}

// round 13
// speedup vs baseline: 4.7130x; 1.1441x over previous
#include <cuda_runtime.h>
#include <cuda_fp16.h>
#include <cstdint>

// Problem constants
#define BATCH 4
#define SEQ   2048
#define DMODEL 1024
#define NHEAD 16
#define HDIM  64
#define SCALE 0.25f

// ---------------------------------------------------------------------------
// Static device scratch (fp16)
// ---------------------------------------------------------------------------
#define QKV_ELEMS ((size_t)BATCH * NHEAD * SEQ * HDIM)
__device__ __half g_Qh[QKV_ELEMS];            // [B,H,L,HD] single fp16
__device__ __half g_Kh[QKV_ELEMS];            // [B,H,L,HD] single fp16
__device__ __half g_Vt[QKV_ELEMS];            // [B,H,HD,L] transposed, single fp16

__device__ __half g_Xh[(size_t)BATCH * SEQ * DMODEL];    // X truncated to fp16
__device__ __half g_Wh[(size_t)3 * DMODEL * DMODEL];     // W fp16 hi
__device__ __half g_Wl[(size_t)3 * DMODEL * DMODEL];     // W fp16 lo

// ---------------------------------------------------------------------------
// Helpers
// ---------------------------------------------------------------------------
__device__ __forceinline__ uint32_t smem_u32(const void* p) {
    uint32_t a;
    asm("{ .reg .u64 t; cvta.to.shared.u64 t, %1; cvt.u32.u64 %0, t; }"
        : "=r"(a) : "l"(p));
    return a;
}

__device__ __forceinline__ void cp16(uint32_t d, const void* s) {
    asm volatile("cp.async.cg.shared.global [%0], [%1], 16;" :: "r"(d), "l"(s) : "memory");
}
#define CP_COMMIT() asm volatile("cp.async.commit_group;" ::: "memory")
#define CP_WAIT(N)  asm volatile("cp.async.wait_group %0;" :: "n"(N) : "memory")

__device__ __forceinline__ uint32_t lds32(uint32_t a) {
    uint32_t v;
    asm volatile("ld.shared.b32 %0, [%1];" : "=r"(v) : "r"(a));
    return v;
}

// fp16 mma: m16n8k16 -> f32
__device__ __forceinline__ void mma16816h(float* c, const uint32_t* a,
                                          uint32_t b0, uint32_t b1) {
    asm volatile(
        "mma.sync.aligned.m16n8k16.row.col.f32.f16.f16.f32 "
        "{%0,%1,%2,%3}, {%4,%5,%6,%7}, {%8,%9}, {%0,%1,%2,%3};"
        : "+f"(c[0]), "+f"(c[1]), "+f"(c[2]), "+f"(c[3])
        : "r"(a[0]), "r"(a[1]), "r"(a[2]), "r"(a[3]), "r"(b0), "r"(b1));
}

// Fast exp on the FMA pipe (x <= 0), rel err ~1e-5.
__device__ __forceinline__ float fexp(float x) {
    x = fmaxf(x, -87.0f);
    const float y = x * 1.44269504f;
    const float fl = floorf(y);
    const float f = y - fl;
    float p = 1.5403530e-4f;
    p = fmaf(p, f, 1.3333558e-3f);
    p = fmaf(p, f, 9.6181291e-3f);
    p = fmaf(p, f, 5.5504109e-2f);
    p = fmaf(p, f, 2.4022651e-1f);
    p = fmaf(p, f, 6.9314718e-1f);
    p = fmaf(p, f, 1.0f);
    return __int_as_float(__float_as_int(p) + (((int)fl) << 23));
}

__device__ __forceinline__ uint32_t pack_h2(float x, float y) {
    __half2 t = __halves2half2(__float2half(x), __float2half(y));
    return *(uint32_t*)&t;
}

// ---------------------------------------------------------------------------
// Fused prep: one launch converts X -> Xh (single) and Wq/Wk/Wv -> Wh+Wl.
// Block ranges: [0,8192) X; [8192+1024*w, ...) W_w (w = 0,1,2).
// ---------------------------------------------------------------------------
__global__ __launch_bounds__(256) void prep_kernel(
    const float* __restrict__ X,
    const float* __restrict__ Wq, const float* __restrict__ Wk,
    const float* __restrict__ Wv)
{
    const int blk = blockIdx.x;
    const int tid = threadIdx.x;
    if (blk < 8192) {
        const int i = blk * 256 + tid;
        float4 v = ((const float4*)X)[i];
        ((__half2*)g_Xh)[2 * i + 0] = __halves2half2(__float2half(v.x), __float2half(v.y));
        ((__half2*)g_Xh)[2 * i + 1] = __halves2half2(__float2half(v.z), __float2half(v.w));
    } else {
        const int w = (blk - 8192) >> 10;
        const int i = ((blk - 8192) & 1023) * 256 + tid;
        const float* src = (w == 0) ? Wq : (w == 1) ? Wk : Wv;
        const size_t off = (size_t)w * DMODEL * DMODEL;
        float4 v = ((const float4*)src)[i];
        float a[4] = {v.x, v.y, v.z, v.w};
        __half h[4], l[4];
        #pragma unroll
        for (int j = 0; j < 4; ++j) {
            h[j] = __float2half(a[j]);
            l[j] = __float2half(a[j] - __half2float(h[j]));
        }
        ((__half2*)(g_Wh + off))[2 * i + 0] = __halves2half2(h[0], h[1]);
        ((__half2*)(g_Wh + off))[2 * i + 1] = __halves2half2(h[2], h[3]);
        ((__half2*)(g_Wl + off))[2 * i + 0] = __halves2half2(l[0], l[1]);
        ((__half2*)(g_Wl + off))[2 * i + 1] = __halves2half2(l[2], l[3]);
    }
}

// ---------------------------------------------------------------------------
// fp16 2-term projection GEMM: C = X16 @ (Wh + Wl)^T + bias.
// CTA 128x128, 8 warps (4x2), warp tile 32x64, kc=32 double-buffered cp.async.
// Epilogue: Q,K single fp16 [B,H,L,HD]; V single fp16 transposed [B,H,HD,L].
// ---------------------------------------------------------------------------
#define PITCH 40
#define ARR_BYTES (128 * PITCH * 2)      // 10240
#define STG_BYTES (3 * ARR_BYTES)        // 30720 (Ah, Bh, Bl)
#define GEMM_SMEM (2 * STG_BYTES)        // 61440

__device__ __forceinline__ void load_stage(
    uint32_t stg, const __half* __restrict__ Xh,
    const __half* __restrict__ Wh, const __half* __restrict__ Wl,
    int rowBase, int colBase, int k0, int tid)
{
    #pragma unroll
    for (int it = 0; it < 6; ++it) {
        const int u = tid + it * 256;          // 0..1535
        const int arr = u >> 9;                // 0:Ah 1:Bh 2:Bl
        const int r = (u >> 2) & 127;
        const int cc = u & 3;
        const __half* src;
        if (arr == 0)      src = Xh + (size_t)(rowBase + r) * DMODEL + k0 + cc * 8;
        else if (arr == 1) src = Wh + (size_t)(colBase + r) * DMODEL + k0 + cc * 8;
        else               src = Wl + (size_t)(colBase + r) * DMODEL + k0 + cc * 8;
        cp16(stg + arr * ARR_BYTES + r * (PITCH * 2) + cc * 16, src);
    }
}

__global__ __launch_bounds__(256) void gemm_kernel(
    const float* __restrict__ bq, const float* __restrict__ bk,
    const float* __restrict__ bv)
{
    extern __shared__ char smem[];
    const uint32_t sb = smem_u32(smem);
    const int tid = threadIdx.x;
    const int warp = tid >> 5;
    const int lane = tid & 31;
    const int g = lane >> 2;
    const int c = lane & 3;
    const int wm = warp >> 1;
    const int wn = warp & 1;

    const int which = blockIdx.z;
    const __half* Wh = g_Wh + (size_t)which * DMODEL * DMODEL;
    const __half* Wl = g_Wl + (size_t)which * DMODEL * DMODEL;
    const float* bias = (which == 0) ? bq : (which == 1) ? bk : bv;
    __half* oh = (which == 0) ? g_Qh : g_Kh;

    const int rowBase = blockIdx.x * 128;
    const int colBase = blockIdx.y * 128;

    float acc[2][8][4] = {};

    load_stage(sb, g_Xh, Wh, Wl, rowBase, colBase, 0, tid);
    CP_COMMIT();

    const uint32_t aRowB = (uint32_t)(wm * 32 + g) * (PITCH * 2) + c * 4;
    const uint32_t bColB = (uint32_t)(wn * 64 + g) * (PITCH * 2) + c * 4;

    for (int sidx = 0; sidx < DMODEL / 32; ++sidx) {
        const uint32_t stg = sb + (uint32_t)(sidx & 1) * STG_BYTES;
        if (sidx + 1 < DMODEL / 32) {
            load_stage(sb + (uint32_t)((sidx + 1) & 1) * STG_BYTES,
                       g_Xh, Wh, Wl, rowBase, colBase, (sidx + 1) * 32, tid);
            CP_COMMIT();
            CP_WAIT(1);
        } else {
            CP_WAIT(0);
        }
        __syncthreads();

        #pragma unroll
        for (int kk = 0; kk < 2; ++kk) {
            const uint32_t ko = kk * 32;
            uint32_t ah[2][4], bh[8][2], bl[8][2];
            #pragma unroll
            for (int mt = 0; mt < 2; ++mt) {
                const uint32_t ba = stg + aRowB + mt * 16 * (PITCH * 2) + ko;
                ah[mt][0] = lds32(ba);
                ah[mt][1] = lds32(ba + 8 * (PITCH * 2));
                ah[mt][2] = lds32(ba + 16);
                ah[mt][3] = lds32(ba + 8 * (PITCH * 2) + 16);
            }
            #pragma unroll
            for (int nt = 0; nt < 8; ++nt) {
                const uint32_t bb = stg + ARR_BYTES + bColB + nt * 8 * (PITCH * 2) + ko;
                bh[nt][0] = lds32(bb);
                bh[nt][1] = lds32(bb + 16);
                bl[nt][0] = lds32(bb + ARR_BYTES);
                bl[nt][1] = lds32(bb + ARR_BYTES + 16);
            }
            #pragma unroll
            for (int mt = 0; mt < 2; ++mt)
                #pragma unroll
                for (int nt = 0; nt < 8; ++nt)
                    mma16816h(acc[mt][nt], ah[mt], bh[nt][0], bh[nt][1]);
            #pragma unroll
            for (int mt = 0; mt < 2; ++mt)
                #pragma unroll
                for (int nt = 0; nt < 8; ++nt)
                    mma16816h(acc[mt][nt], ah[mt], bl[nt][0], bl[nt][1]);
        }
        __syncthreads();
    }

    // Epilogue: bias add, fp32 -> single fp16, scatter
    #pragma unroll
    for (int mt = 0; mt < 2; ++mt) {
        const int row0 = rowBase + wm * 32 + mt * 16 + g;
        #pragma unroll
        for (int nt = 0; nt < 8; ++nt) {
            const int col = colBase + wn * 64 + nt * 8 + 2 * c;
            const float bx = __ldg(&bias[col]);
            const float by = __ldg(&bias[col + 1]);
            const int h = col >> 6, hd = col & 63;
            #pragma unroll
            for (int half = 0; half < 2; ++half) {
                const int row = row0 + half * 8;
                const int b = row >> 11, s = row & 2047;
                const float vx = acc[mt][nt][half * 2 + 0] + bx;
                const float vy = acc[mt][nt][half * 2 + 1] + by;
                if (which < 2) {
                    const size_t o = (((size_t)b * NHEAD + h) * SEQ + s) * HDIM + hd;
                    *(__half2*)&oh[o] =
                        __halves2half2(__float2half(vx), __float2half(vy));
                } else {
                    const size_t o = (((size_t)b * NHEAD + h) * HDIM + hd) * SEQ + s;
                    g_Vt[o] = __float2half(vx);
                    g_Vt[o + SEQ] = __float2half(vy);
                }
            }
        }
    }
}

// ---------------------------------------------------------------------------
// Tensor-core flash attention (causal). CTA = 64 q-rows, 4 warps (m16 each).
// Full single-fp16: S = Q16·K16^T (1 term), O += P16·V16 (1 term).
// ---------------------------------------------------------------------------
#define AP2 144
#define TILEB (64 * AP2)
#define K_O 0
#define V_O TILEB
#define ASTGB (2 * TILEB)       // 18432 per stage
#define ATT_SMEM (2 * ASTGB)    // 36864

__device__ __forceinline__ void load_kv_tile(uint32_t stg, int bh, int key0, int tid)
{
    const __half* kh = g_Kh + ((size_t)bh * SEQ + key0) * HDIM;
    const __half* vt = g_Vt + (size_t)bh * HDIM * SEQ + key0;
    #pragma unroll
    for (int it = 0; it < 4; ++it) {
        const int u = tid + it * 128;
        const int r = u >> 3, cc = u & 7;
        cp16(stg + K_O + r * AP2 + cc * 16, kh + r * HDIM + cc * 8);
        cp16(stg + V_O + r * AP2 + cc * 16, vt + (size_t)r * SEQ + cc * 8);
    }
}

__global__ __launch_bounds__(128) void attn_kernel(float* __restrict__ out)
{
    extern __shared__ char smemc[];
    const uint32_t sb = smem_u32(smemc);
    const int tid = threadIdx.x;
    const int warp = tid >> 5;
    const int lane = tid & 31;
    const int g = lane >> 2;
    const int c = lane & 3;
    const int moff = warp * 16;

    const int bh = blockIdx.y;
    const int b = bh >> 4;
    const int h = bh & 15;
    const int qi = (SEQ / 64 - 1) - blockIdx.x;   // heavy q-tiles first

    // Stage Q (single) into stage-1 K slot; K/V tile 0 into stage 0
    {
        const __half* qh = g_Qh + ((size_t)bh * SEQ + (size_t)qi * 64) * HDIM;
        #pragma unroll
        for (int it = 0; it < 4; ++it) {
            const int u = tid + it * 128;
            const int r = u >> 3, cc = u & 7;
            cp16(sb + ASTGB + K_O + r * AP2 + cc * 16, qh + r * HDIM + cc * 8);
        }
        CP_COMMIT();
        load_kv_tile(sb, bh, 0, tid);
        CP_COMMIT();
    }

    uint32_t qhf[4][4];
    CP_WAIT(1);
    __syncthreads();
    {
        const uint32_t qb = sb + ASTGB + K_O + (uint32_t)(moff + g) * AP2 + c * 4;
        #pragma unroll
        for (int kt = 0; kt < 4; ++kt) {
            qhf[kt][0] = lds32(qb + kt * 32);
            qhf[kt][1] = lds32(qb + kt * 32 + 8 * AP2);
            qhf[kt][2] = lds32(qb + kt * 32 + 16);
            qhf[kt][3] = lds32(qb + kt * 32 + 8 * AP2 + 16);
        }
    }
    __syncthreads();   // Q slot free for pipeline reuse

    float O[8][4] = {};
    float m[2] = {-1e30f, -1e30f};
    float l[2] = {0.0f, 0.0f};

    for (int jb = 0; jb <= qi; ++jb) {
        const uint32_t stg = sb + (uint32_t)(jb & 1) * ASTGB;
        if (jb < qi) {
            load_kv_tile(sb + (uint32_t)((jb + 1) & 1) * ASTGB, bh, (jb + 1) * 64, tid);
            CP_COMMIT();
            CP_WAIT(1);
        } else {
            CP_WAIT(0);
        }
        __syncthreads();

        // ----- S = Q K^T (single fp16) -----
        float S[8][4] = {};
        #pragma unroll
        for (int kt = 0; kt < 4; ++kt) {
            uint32_t bhf[8][2];
            const uint32_t kb = stg + K_O + (uint32_t)g * AP2 + kt * 32 + c * 4;
            #pragma unroll
            for (int nt = 0; nt < 8; ++nt) {
                const uint32_t a0 = kb + nt * 8 * AP2;
                bhf[nt][0] = lds32(a0);
                bhf[nt][1] = lds32(a0 + 16);
            }
            #pragma unroll
            for (int nt = 0; nt < 8; ++nt)
                mma16816h(S[nt], qhf[kt], bhf[nt][0], bhf[nt][1]);
        }

        // ----- scale + causal mask -----
        const bool diag = (jb == qi);
        #pragma unroll
        for (int nt = 0; nt < 8; ++nt) {
            #pragma unroll
            for (int e = 0; e < 4; ++e) {
                float v = S[nt][e] * SCALE;
                if (diag) {
                    const int col = nt * 8 + 2 * c + (e & 1);
                    const int row = moff + g + ((e >> 1) << 3);
                    if (col > row) v = -1e30f;
                }
                S[nt][e] = v;
            }
        }

        // ----- online softmax -----
        float rowm[2] = {-1e30f, -1e30f};
        #pragma unroll
        for (int nt = 0; nt < 8; ++nt) {
            rowm[0] = fmaxf(rowm[0], fmaxf(S[nt][0], S[nt][1]));
            rowm[1] = fmaxf(rowm[1], fmaxf(S[nt][2], S[nt][3]));
        }
        #pragma unroll
        for (int r = 0; r < 2; ++r) {
            rowm[r] = fmaxf(rowm[r], __shfl_xor_sync(0xffffffffu, rowm[r], 1));
            rowm[r] = fmaxf(rowm[r], __shfl_xor_sync(0xffffffffu, rowm[r], 2));
        }
        float corr[2];
        #pragma unroll
        for (int r = 0; r < 2; ++r) {
            const float mnew = fmaxf(m[r], rowm[r]);
            corr[r] = fexp(m[r] - mnew);
            l[r] *= corr[r];
            m[r] = mnew;
        }
        #pragma unroll
        for (int nt = 0; nt < 8; ++nt) {
            O[nt][0] *= corr[0]; O[nt][1] *= corr[0];
            O[nt][2] *= corr[1]; O[nt][3] *= corr[1];
        }
        float psum[2] = {0.0f, 0.0f};
        #pragma unroll
        for (int nt = 0; nt < 8; ++nt) {
            #pragma unroll
            for (int e = 0; e < 4; ++e) {
                const float p = fexp(S[nt][e] - m[e >> 1]);
                S[nt][e] = p;
                psum[e >> 1] += p;
            }
        }
        #pragma unroll
        for (int r = 0; r < 2; ++r) {
            psum[r] += __shfl_xor_sync(0xffffffffu, psum[r], 1);
            psum[r] += __shfl_xor_sync(0xffffffffu, psum[r], 2);
            l[r] += psum[r];
        }

        // ----- P -> single fp16 A-fragments -----
        uint32_t pfp[4][4];
        #pragma unroll
        for (int t = 0; t < 8; ++t) {
            const int kt = t >> 1;
            const int sl = (t & 1) << 1;
            pfp[kt][sl + 0] = pack_h2(S[t][0], S[t][1]);
            pfp[kt][sl + 1] = pack_h2(S[t][2], S[t][3]);
        }

        // ----- O += P V (single fp16) -----
        #pragma unroll
        for (int kt = 0; kt < 4; ++kt) {
            uint32_t vhf[8][2];
            const uint32_t vb = stg + V_O + (uint32_t)g * AP2 + kt * 32 + c * 4;
            #pragma unroll
            for (int nt = 0; nt < 8; ++nt) {
                const uint32_t a0 = vb + nt * 8 * AP2;
                vhf[nt][0] = lds32(a0);
                vhf[nt][1] = lds32(a0 + 16);
            }
            #pragma unroll
            for (int nt = 0; nt < 8; ++nt)
                mma16816h(O[nt], pfp[kt], vhf[nt][0], vhf[nt][1]);
        }
        __syncthreads();
    }

    const float inv0 = 1.0f / l[0];
    const float inv1 = 1.0f / l[1];
    const int row0 = qi * 64 + moff + g;
    #pragma unroll
    for (int nt = 0; nt < 8; ++nt) {
        const int col = h * HDIM + nt * 8 + 2 * c;
        float2 v0 = {O[nt][0] * inv0, O[nt][1] * inv0};
        float2 v1 = {O[nt][2] * inv1, O[nt][3] * inv1};
        *(float2*)&out[((size_t)b * SEQ + row0) * DMODEL + col] = v0;
        *(float2*)&out[((size_t)b * SEQ + row0 + 8) * DMODEL + col] = v1;
    }
}

// ---------------------------------------------------------------------------
extern "C" void kernel_launch(void* const* d_in, const int* in_sizes, int n_in,
                              void* d_out, int out_size)
{
    const float* X  = (const float*)d_in[0];
    const float* Wq = (const float*)d_in[1];
    const float* bq = (const float*)d_in[2];
    const float* Wk = (const float*)d_in[3];
    const float* bk = (const float*)d_in[4];
    const float* Wv = (const float*)d_in[5];
    const float* bv = (const float*)d_in[6];
    float* out = (float*)d_out;

    // Fused prep: X -> fp16, W -> fp16 hi/lo (one launch)
    prep_kernel<<<8192 + 3 * 1024, 256>>>(X, Wq, Wk, Wv);

    cudaFuncSetAttribute(gemm_kernel, cudaFuncAttributeMaxDynamicSharedMemorySize,
                         GEMM_SMEM);
    dim3 gg((BATCH * SEQ) / 128, DMODEL / 128, 3);
    gemm_kernel<<<gg, 256, GEMM_SMEM>>>(bq, bk, bv);

    cudaFuncSetAttribute(attn_kernel, cudaFuncAttributeMaxDynamicSharedMemorySize,
                         ATT_SMEM);
    dim3 ag(SEQ / 64, BATCH * NHEAD);
    attn_kernel<<<ag, 128, ATT_SMEM>>>(out);
}

// round 14
// speedup vs baseline: 5.0979x; 1.0817x over previous
#include <cuda_runtime.h>
#include <cuda_fp16.h>
#include <cstdint>

// Problem constants
#define BATCH 4
#define SEQ   2048
#define DMODEL 1024
#define NHEAD 16
#define HDIM  64
#define SCALE 0.25f

// ---------------------------------------------------------------------------
// Static device scratch (fp16)
// ---------------------------------------------------------------------------
#define QKV_ELEMS ((size_t)BATCH * NHEAD * SEQ * HDIM)
__device__ __half g_Qh[QKV_ELEMS];            // [B,H,L,HD] single fp16
__device__ __half g_Kh[QKV_ELEMS];            // [B,H,L,HD] single fp16
__device__ __half g_Vt[QKV_ELEMS];            // [B,H,HD,L] transposed, single fp16

__device__ __half g_Xh[(size_t)BATCH * SEQ * DMODEL];    // X truncated to fp16
__device__ __half g_Wh[(size_t)3 * DMODEL * DMODEL];     // W fp16 hi
__device__ __half g_Wl[(size_t)3 * DMODEL * DMODEL];     // W fp16 lo

// ---------------------------------------------------------------------------
// Helpers
// ---------------------------------------------------------------------------
__device__ __forceinline__ uint32_t smem_u32(const void* p) {
    uint32_t a;
    asm("{ .reg .u64 t; cvta.to.shared.u64 t, %1; cvt.u32.u64 %0, t; }"
        : "=r"(a) : "l"(p));
    return a;
}

__device__ __forceinline__ void cp16(uint32_t d, const void* s) {
    asm volatile("cp.async.cg.shared.global [%0], [%1], 16;" :: "r"(d), "l"(s) : "memory");
}
#define CP_COMMIT() asm volatile("cp.async.commit_group;" ::: "memory")
#define CP_WAIT(N)  asm volatile("cp.async.wait_group %0;" :: "n"(N) : "memory")

__device__ __forceinline__ uint32_t lds32(uint32_t a) {
    uint32_t v;
    asm volatile("ld.shared.b32 %0, [%1];" : "=r"(v) : "r"(a));
    return v;
}

// fp16 mma: m16n8k16 -> f32
__device__ __forceinline__ void mma16816h(float* c, const uint32_t* a,
                                          uint32_t b0, uint32_t b1) {
    asm volatile(
        "mma.sync.aligned.m16n8k16.row.col.f32.f16.f16.f32 "
        "{%0,%1,%2,%3}, {%4,%5,%6,%7}, {%8,%9}, {%0,%1,%2,%3};"
        : "+f"(c[0]), "+f"(c[1]), "+f"(c[2]), "+f"(c[3])
        : "r"(a[0]), "r"(a[1]), "r"(a[2]), "r"(a[3]), "r"(b0), "r"(b1));
}

// Fast exp on the FMA pipe (x <= 0), rel err ~1e-5.
__device__ __forceinline__ float fexp(float x) {
    x = fmaxf(x, -87.0f);
    const float y = x * 1.44269504f;
    const float fl = floorf(y);
    const float f = y - fl;
    float p = 1.5403530e-4f;
    p = fmaf(p, f, 1.3333558e-3f);
    p = fmaf(p, f, 9.6181291e-3f);
    p = fmaf(p, f, 5.5504109e-2f);
    p = fmaf(p, f, 2.4022651e-1f);
    p = fmaf(p, f, 6.9314718e-1f);
    p = fmaf(p, f, 1.0f);
    return __int_as_float(__float_as_int(p) + (((int)fl) << 23));
}

__device__ __forceinline__ uint32_t pack_h2(float x, float y) {
    __half2 t = __halves2half2(__float2half(x), __float2half(y));
    return *(uint32_t*)&t;
}

// ---------------------------------------------------------------------------
// Fused prep: one launch converts X -> Xh (single) and Wq/Wk/Wv -> Wh+Wl.
// ---------------------------------------------------------------------------
__global__ __launch_bounds__(256) void prep_kernel(
    const float* __restrict__ X,
    const float* __restrict__ Wq, const float* __restrict__ Wk,
    const float* __restrict__ Wv)
{
    const int blk = blockIdx.x;
    const int tid = threadIdx.x;
    if (blk < 8192) {
        const int i = blk * 256 + tid;
        float4 v = ((const float4*)X)[i];
        ((__half2*)g_Xh)[2 * i + 0] = __halves2half2(__float2half(v.x), __float2half(v.y));
        ((__half2*)g_Xh)[2 * i + 1] = __halves2half2(__float2half(v.z), __float2half(v.w));
    } else {
        const int w = (blk - 8192) >> 10;
        const int i = ((blk - 8192) & 1023) * 256 + tid;
        const float* src = (w == 0) ? Wq : (w == 1) ? Wk : Wv;
        const size_t off = (size_t)w * DMODEL * DMODEL;
        float4 v = ((const float4*)src)[i];
        float a[4] = {v.x, v.y, v.z, v.w};
        __half h[4], l[4];
        #pragma unroll
        for (int j = 0; j < 4; ++j) {
            h[j] = __float2half(a[j]);
            l[j] = __float2half(a[j] - __half2float(h[j]));
        }
        ((__half2*)(g_Wh + off))[2 * i + 0] = __halves2half2(h[0], h[1]);
        ((__half2*)(g_Wh + off))[2 * i + 1] = __halves2half2(h[2], h[3]);
        ((__half2*)(g_Wl + off))[2 * i + 0] = __halves2half2(l[0], l[1]);
        ((__half2*)(g_Wl + off))[2 * i + 1] = __halves2half2(l[2], l[3]);
    }
}

// ---------------------------------------------------------------------------
// fp16 projection GEMM: C = X16 @ (Wh [+ Wl])^T + bias.
// Q,K use 2-term (Wh+Wl); V uses 1-term (Wh only) — V noise passes linearly
// through the softmax average, so the dropped term is harmless there.
// CTA 128x128, 8 warps (4x2), warp tile 32x64, kc=32 double-buffered cp.async.
// ---------------------------------------------------------------------------
#define PITCH 40
#define ARR_BYTES (128 * PITCH * 2)      // 10240
#define STG_BYTES (3 * ARR_BYTES)        // 30720 (Ah, Bh, Bl)
#define GEMM_SMEM (2 * STG_BYTES)        // 61440

__device__ __forceinline__ void load_stage(
    uint32_t stg, const __half* __restrict__ Xh,
    const __half* __restrict__ Wh, const __half* __restrict__ Wl,
    int rowBase, int colBase, int k0, int tid, int useBl)
{
    #pragma unroll
    for (int it = 0; it < 6; ++it) {
        const int u = tid + it * 256;          // 0..1535
        const int arr = u >> 9;                // 0:Ah 1:Bh 2:Bl
        if (arr == 2 && !useBl) continue;
        const int r = (u >> 2) & 127;
        const int cc = u & 3;
        const __half* src;
        if (arr == 0)      src = Xh + (size_t)(rowBase + r) * DMODEL + k0 + cc * 8;
        else if (arr == 1) src = Wh + (size_t)(colBase + r) * DMODEL + k0 + cc * 8;
        else               src = Wl + (size_t)(colBase + r) * DMODEL + k0 + cc * 8;
        cp16(stg + arr * ARR_BYTES + r * (PITCH * 2) + cc * 16, src);
    }
}

__global__ __launch_bounds__(256) void gemm_kernel(
    const float* __restrict__ bq, const float* __restrict__ bk,
    const float* __restrict__ bv)
{
    extern __shared__ char smem[];
    const uint32_t sb = smem_u32(smem);
    const int tid = threadIdx.x;
    const int warp = tid >> 5;
    const int lane = tid & 31;
    const int g = lane >> 2;
    const int c = lane & 3;
    const int wm = warp >> 1;
    const int wn = warp & 1;

    const int which = blockIdx.z;
    const int useBl = (which < 2);     // V projection: 1-term
    const __half* Wh = g_Wh + (size_t)which * DMODEL * DMODEL;
    const __half* Wl = g_Wl + (size_t)which * DMODEL * DMODEL;
    const float* bias = (which == 0) ? bq : (which == 1) ? bk : bv;
    __half* oh = (which == 0) ? g_Qh : g_Kh;

    const int rowBase = blockIdx.x * 128;
    const int colBase = blockIdx.y * 128;

    float acc[2][8][4] = {};

    load_stage(sb, g_Xh, Wh, Wl, rowBase, colBase, 0, tid, useBl);
    CP_COMMIT();

    const uint32_t aRowB = (uint32_t)(wm * 32 + g) * (PITCH * 2) + c * 4;
    const uint32_t bColB = (uint32_t)(wn * 64 + g) * (PITCH * 2) + c * 4;

    for (int sidx = 0; sidx < DMODEL / 32; ++sidx) {
        const uint32_t stg = sb + (uint32_t)(sidx & 1) * STG_BYTES;
        if (sidx + 1 < DMODEL / 32) {
            load_stage(sb + (uint32_t)((sidx + 1) & 1) * STG_BYTES,
                       g_Xh, Wh, Wl, rowBase, colBase, (sidx + 1) * 32, tid, useBl);
            CP_COMMIT();
            CP_WAIT(1);
        } else {
            CP_WAIT(0);
        }
        __syncthreads();

        #pragma unroll
        for (int kk = 0; kk < 2; ++kk) {
            const uint32_t ko = kk * 32;
            uint32_t ah[2][4], bh[8][2], bl[8][2];
            #pragma unroll
            for (int mt = 0; mt < 2; ++mt) {
                const uint32_t ba = stg + aRowB + mt * 16 * (PITCH * 2) + ko;
                ah[mt][0] = lds32(ba);
                ah[mt][1] = lds32(ba + 8 * (PITCH * 2));
                ah[mt][2] = lds32(ba + 16);
                ah[mt][3] = lds32(ba + 8 * (PITCH * 2) + 16);
            }
            #pragma unroll
            for (int nt = 0; nt < 8; ++nt) {
                const uint32_t bb = stg + ARR_BYTES + bColB + nt * 8 * (PITCH * 2) + ko;
                bh[nt][0] = lds32(bb);
                bh[nt][1] = lds32(bb + 16);
            }
            #pragma unroll
            for (int mt = 0; mt < 2; ++mt)
                #pragma unroll
                for (int nt = 0; nt < 8; ++nt)
                    mma16816h(acc[mt][nt], ah[mt], bh[nt][0], bh[nt][1]);
            if (useBl) {
                #pragma unroll
                for (int nt = 0; nt < 8; ++nt) {
                    const uint32_t bb = stg + 2 * ARR_BYTES + bColB + nt * 8 * (PITCH * 2) + ko;
                    bl[nt][0] = lds32(bb);
                    bl[nt][1] = lds32(bb + 16);
                }
                #pragma unroll
                for (int mt = 0; mt < 2; ++mt)
                    #pragma unroll
                    for (int nt = 0; nt < 8; ++nt)
                        mma16816h(acc[mt][nt], ah[mt], bl[nt][0], bl[nt][1]);
            }
        }
        __syncthreads();
    }

    // Epilogue: bias add, fp32 -> single fp16, scatter
    #pragma unroll
    for (int mt = 0; mt < 2; ++mt) {
        const int row0 = rowBase + wm * 32 + mt * 16 + g;
        #pragma unroll
        for (int nt = 0; nt < 8; ++nt) {
            const int col = colBase + wn * 64 + nt * 8 + 2 * c;
            const float bx = __ldg(&bias[col]);
            const float by = __ldg(&bias[col + 1]);
            const int h = col >> 6, hd = col & 63;
            #pragma unroll
            for (int half = 0; half < 2; ++half) {
                const int row = row0 + half * 8;
                const int b = row >> 11, s = row & 2047;
                const float vx = acc[mt][nt][half * 2 + 0] + bx;
                const float vy = acc[mt][nt][half * 2 + 1] + by;
                if (which < 2) {
                    const size_t o = (((size_t)b * NHEAD + h) * SEQ + s) * HDIM + hd;
                    *(__half2*)&oh[o] =
                        __halves2half2(__float2half(vx), __float2half(vy));
                } else {
                    const size_t o = (((size_t)b * NHEAD + h) * HDIM + hd) * SEQ + s;
                    g_Vt[o] = __float2half(vx);
                    g_Vt[o + SEQ] = __float2half(vy);
                }
            }
        }
    }
}

// ---------------------------------------------------------------------------
// Tensor-core flash attention (causal). CTA = 64 q-rows, 4 warps (m16 each).
// Full single-fp16: S = Q16·K16^T (1 term), O += P16·V16 (1 term).
// (Unchanged from the 553 us version.)
// ---------------------------------------------------------------------------
#define AP2 144
#define TILEB (64 * AP2)
#define K_O 0
#define V_O TILEB
#define ASTGB (2 * TILEB)       // 18432 per stage
#define ATT_SMEM (2 * ASTGB)    // 36864

__device__ __forceinline__ void load_kv_tile(uint32_t stg, int bh, int key0, int tid)
{
    const __half* kh = g_Kh + ((size_t)bh * SEQ + key0) * HDIM;
    const __half* vt = g_Vt + (size_t)bh * HDIM * SEQ + key0;
    #pragma unroll
    for (int it = 0; it < 4; ++it) {
        const int u = tid + it * 128;
        const int r = u >> 3, cc = u & 7;
        cp16(stg + K_O + r * AP2 + cc * 16, kh + r * HDIM + cc * 8);
        cp16(stg + V_O + r * AP2 + cc * 16, vt + (size_t)r * SEQ + cc * 8);
    }
}

__global__ __launch_bounds__(128) void attn_kernel(float* __restrict__ out)
{
    extern __shared__ char smemc[];
    const uint32_t sb = smem_u32(smemc);
    const int tid = threadIdx.x;
    const int warp = tid >> 5;
    const int lane = tid & 31;
    const int g = lane >> 2;
    const int c = lane & 3;
    const int moff = warp * 16;

    const int bh = blockIdx.y;
    const int b = bh >> 4;
    const int h = bh & 15;
    const int qi = (SEQ / 64 - 1) - blockIdx.x;   // heavy q-tiles first

    // Stage Q (single) into stage-1 K slot; K/V tile 0 into stage 0
    {
        const __half* qh = g_Qh + ((size_t)bh * SEQ + (size_t)qi * 64) * HDIM;
        #pragma unroll
        for (int it = 0; it < 4; ++it) {
            const int u = tid + it * 128;
            const int r = u >> 3, cc = u & 7;
            cp16(sb + ASTGB + K_O + r * AP2 + cc * 16, qh + r * HDIM + cc * 8);
        }
        CP_COMMIT();
        load_kv_tile(sb, bh, 0, tid);
        CP_COMMIT();
    }

    uint32_t qhf[4][4];
    CP_WAIT(1);
    __syncthreads();
    {
        const uint32_t qb = sb + ASTGB + K_O + (uint32_t)(moff + g) * AP2 + c * 4;
        #pragma unroll
        for (int kt = 0; kt < 4; ++kt) {
            qhf[kt][0] = lds32(qb + kt * 32);
            qhf[kt][1] = lds32(qb + kt * 32 + 8 * AP2);
            qhf[kt][2] = lds32(qb + kt * 32 + 16);
            qhf[kt][3] = lds32(qb + kt * 32 + 8 * AP2 + 16);
        }
    }
    __syncthreads();   // Q slot free for pipeline reuse

    float O[8][4] = {};
    float m[2] = {-1e30f, -1e30f};
    float l[2] = {0.0f, 0.0f};

    for (int jb = 0; jb <= qi; ++jb) {
        const uint32_t stg = sb + (uint32_t)(jb & 1) * ASTGB;
        if (jb < qi) {
            load_kv_tile(sb + (uint32_t)((jb + 1) & 1) * ASTGB, bh, (jb + 1) * 64, tid);
            CP_COMMIT();
            CP_WAIT(1);
        } else {
            CP_WAIT(0);
        }
        __syncthreads();

        // ----- S = Q K^T (single fp16) -----
        float S[8][4] = {};
        #pragma unroll
        for (int kt = 0; kt < 4; ++kt) {
            uint32_t bhf[8][2];
            const uint32_t kb = stg + K_O + (uint32_t)g * AP2 + kt * 32 + c * 4;
            #pragma unroll
            for (int nt = 0; nt < 8; ++nt) {
                const uint32_t a0 = kb + nt * 8 * AP2;
                bhf[nt][0] = lds32(a0);
                bhf[nt][1] = lds32(a0 + 16);
            }
            #pragma unroll
            for (int nt = 0; nt < 8; ++nt)
                mma16816h(S[nt], qhf[kt], bhf[nt][0], bhf[nt][1]);
        }

        // ----- scale + causal mask -----
        const bool diag = (jb == qi);
        #pragma unroll
        for (int nt = 0; nt < 8; ++nt) {
            #pragma unroll
            for (int e = 0; e < 4; ++e) {
                float v = S[nt][e] * SCALE;
                if (diag) {
                    const int col = nt * 8 + 2 * c + (e & 1);
                    const int row = moff + g + ((e >> 1) << 3);
                    if (col > row) v = -1e30f;
                }
                S[nt][e] = v;
            }
        }

        // ----- online softmax -----
        float rowm[2] = {-1e30f, -1e30f};
        #pragma unroll
        for (int nt = 0; nt < 8; ++nt) {
            rowm[0] = fmaxf(rowm[0], fmaxf(S[nt][0], S[nt][1]));
            rowm[1] = fmaxf(rowm[1], fmaxf(S[nt][2], S[nt][3]));
        }
        #pragma unroll
        for (int r = 0; r < 2; ++r) {
            rowm[r] = fmaxf(rowm[r], __shfl_xor_sync(0xffffffffu, rowm[r], 1));
            rowm[r] = fmaxf(rowm[r], __shfl_xor_sync(0xffffffffu, rowm[r], 2));
        }
        float corr[2];
        #pragma unroll
        for (int r = 0; r < 2; ++r) {
            const float mnew = fmaxf(m[r], rowm[r]);
            corr[r] = fexp(m[r] - mnew);
            l[r] *= corr[r];
            m[r] = mnew;
        }
        #pragma unroll
        for (int nt = 0; nt < 8; ++nt) {
            O[nt][0] *= corr[0]; O[nt][1] *= corr[0];
            O[nt][2] *= corr[1]; O[nt][3] *= corr[1];
        }
        float psum[2] = {0.0f, 0.0f};
        #pragma unroll
        for (int nt = 0; nt < 8; ++nt) {
            #pragma unroll
            for (int e = 0; e < 4; ++e) {
                const float p = fexp(S[nt][e] - m[e >> 1]);
                S[nt][e] = p;
                psum[e >> 1] += p;
            }
        }
        #pragma unroll
        for (int r = 0; r < 2; ++r) {
            psum[r] += __shfl_xor_sync(0xffffffffu, psum[r], 1);
            psum[r] += __shfl_xor_sync(0xffffffffu, psum[r], 2);
            l[r] += psum[r];
        }

        // ----- P -> single fp16 A-fragments -----
        uint32_t pfp[4][4];
        #pragma unroll
        for (int t = 0; t < 8; ++t) {
            const int kt = t >> 1;
            const int sl = (t & 1) << 1;
            pfp[kt][sl + 0] = pack_h2(S[t][0], S[t][1]);
            pfp[kt][sl + 1] = pack_h2(S[t][2], S[t][3]);
        }

        // ----- O += P V (single fp16) -----
        #pragma unroll
        for (int kt = 0; kt < 4; ++kt) {
            uint32_t vhf[8][2];
            const uint32_t vb = stg + V_O + (uint32_t)g * AP2 + kt * 32 + c * 4;
            #pragma unroll
            for (int nt = 0; nt < 8; ++nt) {
                const uint32_t a0 = vb + nt * 8 * AP2;
                vhf[nt][0] = lds32(a0);
                vhf[nt][1] = lds32(a0 + 16);
            }
            #pragma unroll
            for (int nt = 0; nt < 8; ++nt)
                mma16816h(O[nt], pfp[kt], vhf[nt][0], vhf[nt][1]);
        }
        __syncthreads();
    }

    const float inv0 = 1.0f / l[0];
    const float inv1 = 1.0f / l[1];
    const int row0 = qi * 64 + moff + g;
    #pragma unroll
    for (int nt = 0; nt < 8; ++nt) {
        const int col = h * HDIM + nt * 8 + 2 * c;
        float2 v0 = {O[nt][0] * inv0, O[nt][1] * inv0};
        float2 v1 = {O[nt][2] * inv1, O[nt][3] * inv1};
        *(float2*)&out[((size_t)b * SEQ + row0) * DMODEL + col] = v0;
        *(float2*)&out[((size_t)b * SEQ + row0 + 8) * DMODEL + col] = v1;
    }
}

// ---------------------------------------------------------------------------
extern "C" void kernel_launch(void* const* d_in, const int* in_sizes, int n_in,
                              void* d_out, int out_size)
{
    const float* X  = (const float*)d_in[0];
    const float* Wq = (const float*)d_in[1];
    const float* bq = (const float*)d_in[2];
    const float* Wk = (const float*)d_in[3];
    const float* bk = (const float*)d_in[4];
    const float* Wv = (const float*)d_in[5];
    const float* bv = (const float*)d_in[6];
    float* out = (float*)d_out;

    // Fused prep: X -> fp16, W -> fp16 hi/lo (one launch)
    prep_kernel<<<8192 + 3 * 1024, 256>>>(X, Wq, Wk, Wv);

    cudaFuncSetAttribute(gemm_kernel, cudaFuncAttributeMaxDynamicSharedMemorySize,
                         GEMM_SMEM);
    dim3 gg((BATCH * SEQ) / 128, DMODEL / 128, 3);
    gemm_kernel<<<gg, 256, GEMM_SMEM>>>(bq, bk, bv);

    cudaFuncSetAttribute(attn_kernel, cudaFuncAttributeMaxDynamicSharedMemorySize,
                         ATT_SMEM);
    dim3 ag(SEQ / 64, BATCH * NHEAD);
    attn_kernel<<<ag, 128, ATT_SMEM>>>(out);
}

// round 17
// speedup vs baseline: 5.2784x; 1.0354x over previous
#include <cuda_runtime.h>
#include <cuda_fp16.h>
#include <cstdint>

// Problem constants
#define BATCH 4
#define SEQ   2048
#define DMODEL 1024
#define NHEAD 16
#define HDIM  64
#define SCALE 0.25f

// ---------------------------------------------------------------------------
// Static device scratch (fp16)
// ---------------------------------------------------------------------------
#define QKV_ELEMS ((size_t)BATCH * NHEAD * SEQ * HDIM)
__device__ __half g_Qh[QKV_ELEMS];            // [B,H,L,HD] single fp16, pre-scaled by SCALE
__device__ __half g_Kh[QKV_ELEMS];            // [B,H,L,HD] single fp16
__device__ __half g_Vt[QKV_ELEMS];            // [B,H,HD,L] transposed, single fp16

__device__ __half g_Xh[(size_t)BATCH * SEQ * DMODEL];    // X truncated to fp16
__device__ __half g_Wh[(size_t)3 * DMODEL * DMODEL];     // W fp16 hi
__device__ __half g_Wl[(size_t)3 * DMODEL * DMODEL];     // W fp16 lo

// ---------------------------------------------------------------------------
// Helpers
// ---------------------------------------------------------------------------
__device__ __forceinline__ uint32_t smem_u32(const void* p) {
    uint32_t a;
    asm("{ .reg .u64 t; cvta.to.shared.u64 t, %1; cvt.u32.u64 %0, t; }"
        : "=r"(a) : "l"(p));
    return a;
}

__device__ __forceinline__ void cp16(uint32_t d, const void* s) {
    asm volatile("cp.async.cg.shared.global [%0], [%1], 16;" :: "r"(d), "l"(s) : "memory");
}
#define CP_COMMIT() asm volatile("cp.async.commit_group;" ::: "memory")
#define CP_WAIT(N)  asm volatile("cp.async.wait_group %0;" :: "n"(N) : "memory")

__device__ __forceinline__ uint32_t lds32(uint32_t a) {
    uint32_t v;
    asm volatile("ld.shared.b32 %0, [%1];" : "=r"(v) : "r"(a));
    return v;
}

// fp16 mma: m16n8k16 -> f32
__device__ __forceinline__ void mma16816h(float* c, const uint32_t* a,
                                          uint32_t b0, uint32_t b1) {
    asm volatile(
        "mma.sync.aligned.m16n8k16.row.col.f32.f16.f16.f32 "
        "{%0,%1,%2,%3}, {%4,%5,%6,%7}, {%8,%9}, {%0,%1,%2,%3};"
        : "+f"(c[0]), "+f"(c[1]), "+f"(c[2]), "+f"(c[3])
        : "r"(a[0]), "r"(a[1]), "r"(a[2]), "r"(a[3]), "r"(b0), "r"(b1));
}

// Fast exp on the FMA pipe (x <= 0), rel err ~1e-5.
__device__ __forceinline__ float fexp(float x) {
    x = fmaxf(x, -87.0f);
    const float y = x * 1.44269504f;
    const float fl = floorf(y);
    const float f = y - fl;
    float p = 1.5403530e-4f;
    p = fmaf(p, f, 1.3333558e-3f);
    p = fmaf(p, f, 9.6181291e-3f);
    p = fmaf(p, f, 5.5504109e-2f);
    p = fmaf(p, f, 2.4022651e-1f);
    p = fmaf(p, f, 6.9314718e-1f);
    p = fmaf(p, f, 1.0f);
    return __int_as_float(__float_as_int(p) + (((int)fl) << 23));
}

__device__ __forceinline__ uint32_t pack_h2(float x, float y) {
    __half2 t = __halves2half2(__float2half(x), __float2half(y));
    return *(uint32_t*)&t;
}

// ---------------------------------------------------------------------------
// Fused prep: one launch converts X -> Xh (single) and Wq/Wk/Wv -> Wh+Wl.
// ---------------------------------------------------------------------------
__global__ __launch_bounds__(256) void prep_kernel(
    const float* __restrict__ X,
    const float* __restrict__ Wq, const float* __restrict__ Wk,
    const float* __restrict__ Wv)
{
    const int blk = blockIdx.x;
    const int tid = threadIdx.x;
    if (blk < 8192) {
        const int i = blk * 256 + tid;
        float4 v = ((const float4*)X)[i];
        ((__half2*)g_Xh)[2 * i + 0] = __halves2half2(__float2half(v.x), __float2half(v.y));
        ((__half2*)g_Xh)[2 * i + 1] = __halves2half2(__float2half(v.z), __float2half(v.w));
    } else {
        const int w = (blk - 8192) >> 10;
        const int i = ((blk - 8192) & 1023) * 256 + tid;
        const float* src = (w == 0) ? Wq : (w == 1) ? Wk : Wv;
        const size_t off = (size_t)w * DMODEL * DMODEL;
        float4 v = ((const float4*)src)[i];
        float a[4] = {v.x, v.y, v.z, v.w};
        __half h[4], l[4];
        #pragma unroll
        for (int j = 0; j < 4; ++j) {
            h[j] = __float2half(a[j]);
            l[j] = __float2half(a[j] - __half2float(h[j]));
        }
        ((__half2*)(g_Wh + off))[2 * i + 0] = __halves2half2(h[0], h[1]);
        ((__half2*)(g_Wh + off))[2 * i + 1] = __halves2half2(h[2], h[3]);
        ((__half2*)(g_Wl + off))[2 * i + 0] = __halves2half2(l[0], l[1]);
        ((__half2*)(g_Wl + off))[2 * i + 1] = __halves2half2(l[2], l[3]);
    }
}

// ---------------------------------------------------------------------------
// fp16 projection GEMM: C = X16 @ (Wh [+ Wl])^T + bias.
// Q,K 2-term; V 1-term. Q epilogue pre-multiplies by SCALE.
// ---------------------------------------------------------------------------
#define PITCH 40
#define ARR_BYTES (128 * PITCH * 2)      // 10240
#define STG_BYTES (3 * ARR_BYTES)        // 30720 (Ah, Bh, Bl)
#define GEMM_SMEM (2 * STG_BYTES)        // 61440

__device__ __forceinline__ void load_stage(
    uint32_t stg, const __half* __restrict__ Xh,
    const __half* __restrict__ Wh, const __half* __restrict__ Wl,
    int rowBase, int colBase, int k0, int tid, int useBl)
{
    #pragma unroll
    for (int it = 0; it < 6; ++it) {
        const int u = tid + it * 256;          // 0..1535
        const int arr = u >> 9;                // 0:Ah 1:Bh 2:Bl
        if (arr == 2 && !useBl) continue;
        const int r = (u >> 2) & 127;
        const int cc = u & 3;
        const __half* src;
        if (arr == 0)      src = Xh + (size_t)(rowBase + r) * DMODEL + k0 + cc * 8;
        else if (arr == 1) src = Wh + (size_t)(colBase + r) * DMODEL + k0 + cc * 8;
        else               src = Wl + (size_t)(colBase + r) * DMODEL + k0 + cc * 8;
        cp16(stg + arr * ARR_BYTES + r * (PITCH * 2) + cc * 16, src);
    }
}

__global__ __launch_bounds__(256) void gemm_kernel(
    const float* __restrict__ bq, const float* __restrict__ bk,
    const float* __restrict__ bv)
{
    extern __shared__ char smem[];
    const uint32_t sb = smem_u32(smem);
    const int tid = threadIdx.x;
    const int warp = tid >> 5;
    const int lane = tid & 31;
    const int g = lane >> 2;
    const int c = lane & 3;
    const int wm = warp >> 1;
    const int wn = warp & 1;

    const int which = blockIdx.z;
    const int useBl = (which < 2);     // V projection: 1-term
    const __half* Wh = g_Wh + (size_t)which * DMODEL * DMODEL;
    const __half* Wl = g_Wl + (size_t)which * DMODEL * DMODEL;
    const float* bias = (which == 0) ? bq : (which == 1) ? bk : bv;
    __half* oh = (which == 0) ? g_Qh : g_Kh;
    const float oscale = (which == 0) ? SCALE : 1.0f;

    const int rowBase = blockIdx.x * 128;
    const int colBase = blockIdx.y * 128;

    float acc[2][8][4] = {};

    load_stage(sb, g_Xh, Wh, Wl, rowBase, colBase, 0, tid, useBl);
    CP_COMMIT();

    const uint32_t aRowB = (uint32_t)(wm * 32 + g) * (PITCH * 2) + c * 4;
    const uint32_t bColB = (uint32_t)(wn * 64 + g) * (PITCH * 2) + c * 4;

    for (int sidx = 0; sidx < DMODEL / 32; ++sidx) {
        const uint32_t stg = sb + (uint32_t)(sidx & 1) * STG_BYTES;
        if (sidx + 1 < DMODEL / 32) {
            load_stage(sb + (uint32_t)((sidx + 1) & 1) * STG_BYTES,
                       g_Xh, Wh, Wl, rowBase, colBase, (sidx + 1) * 32, tid, useBl);
            CP_COMMIT();
            CP_WAIT(1);
        } else {
            CP_WAIT(0);
        }
        __syncthreads();

        #pragma unroll
        for (int kk = 0; kk < 2; ++kk) {
            const uint32_t ko = kk * 32;
            uint32_t ah[2][4], bh[8][2], bl[8][2];
            #pragma unroll
            for (int mt = 0; mt < 2; ++mt) {
                const uint32_t ba = stg + aRowB + mt * 16 * (PITCH * 2) + ko;
                ah[mt][0] = lds32(ba);
                ah[mt][1] = lds32(ba + 8 * (PITCH * 2));
                ah[mt][2] = lds32(ba + 16);
                ah[mt][3] = lds32(ba + 8 * (PITCH * 2) + 16);
            }
            #pragma unroll
            for (int nt = 0; nt < 8; ++nt) {
                const uint32_t bb = stg + ARR_BYTES + bColB + nt * 8 * (PITCH * 2) + ko;
                bh[nt][0] = lds32(bb);
                bh[nt][1] = lds32(bb + 16);
            }
            #pragma unroll
            for (int mt = 0; mt < 2; ++mt)
                #pragma unroll
                for (int nt = 0; nt < 8; ++nt)
                    mma16816h(acc[mt][nt], ah[mt], bh[nt][0], bh[nt][1]);
            if (useBl) {
                #pragma unroll
                for (int nt = 0; nt < 8; ++nt) {
                    const uint32_t bb = stg + 2 * ARR_BYTES + bColB + nt * 8 * (PITCH * 2) + ko;
                    bl[nt][0] = lds32(bb);
                    bl[nt][1] = lds32(bb + 16);
                }
                #pragma unroll
                for (int mt = 0; mt < 2; ++mt)
                    #pragma unroll
                    for (int nt = 0; nt < 8; ++nt)
                        mma16816h(acc[mt][nt], ah[mt], bl[nt][0], bl[nt][1]);
            }
        }
        __syncthreads();
    }

    // Epilogue: bias add (Q also scaled by SCALE), fp32 -> fp16, scatter
    #pragma unroll
    for (int mt = 0; mt < 2; ++mt) {
        const int row0 = rowBase + wm * 32 + mt * 16 + g;
        #pragma unroll
        for (int nt = 0; nt < 8; ++nt) {
            const int col = colBase + wn * 64 + nt * 8 + 2 * c;
            const float bx = __ldg(&bias[col]);
            const float by = __ldg(&bias[col + 1]);
            const int h = col >> 6, hd = col & 63;
            #pragma unroll
            for (int half = 0; half < 2; ++half) {
                const int row = row0 + half * 8;
                const int b = row >> 11, s = row & 2047;
                const float vx = (acc[mt][nt][half * 2 + 0] + bx) * oscale;
                const float vy = (acc[mt][nt][half * 2 + 1] + by) * oscale;
                if (which < 2) {
                    const size_t o = (((size_t)b * NHEAD + h) * SEQ + s) * HDIM + hd;
                    *(__half2*)&oh[o] =
                        __halves2half2(__float2half(vx), __float2half(vy));
                } else {
                    const size_t o = (((size_t)b * NHEAD + h) * HDIM + hd) * SEQ + s;
                    g_Vt[o] = __float2half(vx);
                    g_Vt[o + SEQ] = __float2half(vy);
                }
            }
        }
    }
}

// ---------------------------------------------------------------------------
// Tensor-core flash attention (causal). CTA = 64 q-rows, 4 warps (m16 each).
// KT = 128 keys per double-buffered block. Single-fp16 S and PV.
// SCALE pre-folded into Q; l kept lane-partial until the epilogue.
// ---------------------------------------------------------------------------
#define KP2 144                      // K tile row pitch (128B data + 16 pad)
#define VP2 272                      // V tile row pitch (256B data + 16 pad)
#define KTILE (128 * KP2)            // 18432
#define VTILE (64 * VP2)             // 17408
#define K_O 0
#define V_O KTILE
#define ASTGB (KTILE + VTILE)        // 35840 per stage
#define ATT_SMEM (2 * ASTGB)         // 71680

__device__ __forceinline__ void load_kv_tile(uint32_t stg, int bh, int key0, int tid)
{
    const __half* kh = g_Kh + ((size_t)bh * SEQ + key0) * HDIM;
    const __half* vt = g_Vt + (size_t)bh * HDIM * SEQ + key0;
    #pragma unroll
    for (int it = 0; it < 8; ++it) {           // K: 128 rows x 8 chunks
        const int u = tid + it * 128;
        const int r = u >> 3, cc = u & 7;
        cp16(stg + K_O + r * KP2 + cc * 16, kh + r * HDIM + cc * 8);
    }
    #pragma unroll
    for (int it = 0; it < 8; ++it) {           // V: 64 rows x 16 chunks
        const int u = tid + it * 128;
        const int r = u >> 4, cc = u & 15;
        cp16(stg + V_O + r * VP2 + cc * 16, vt + (size_t)r * SEQ + cc * 8);
    }
}

__global__ __launch_bounds__(128, 3) void attn_kernel(float* __restrict__ out)
{
    extern __shared__ char smemc[];
    const uint32_t sb = smem_u32(smemc);
    const int tid = threadIdx.x;
    const int warp = tid >> 5;
    const int lane = tid & 31;
    const int g = lane >> 2;
    const int c = lane & 3;
    const int moff = warp * 16;

    const int bh = blockIdx.y;
    const int b = bh >> 4;
    const int h = bh & 15;
    const int qi = (SEQ / 64 - 1) - blockIdx.x;   // heavy q-tiles first
    const int nblk = (qi >> 1) + 1;               // 128-key blocks

    // Stage Q (single, pre-scaled) into stage-1 K region; K/V block 0 into stage 0
    {
        const __half* qh = g_Qh + ((size_t)bh * SEQ + (size_t)qi * 64) * HDIM;
        #pragma unroll
        for (int it = 0; it < 4; ++it) {
            const int u = tid + it * 128;
            const int r = u >> 3, cc = u & 7;
            cp16(sb + ASTGB + K_O + r * KP2 + cc * 16, qh + r * HDIM + cc * 8);
        }
        CP_COMMIT();
        load_kv_tile(sb, bh, 0, tid);
        CP_COMMIT();
    }

    uint32_t qhf[4][4];
    CP_WAIT(1);
    __syncthreads();
    {
        const uint32_t qb = sb + ASTGB + K_O + (uint32_t)(moff + g) * KP2 + c * 4;
        #pragma unroll
        for (int kt = 0; kt < 4; ++kt) {
            qhf[kt][0] = lds32(qb + kt * 32);
            qhf[kt][1] = lds32(qb + kt * 32 + 8 * KP2);
            qhf[kt][2] = lds32(qb + kt * 32 + 16);
            qhf[kt][3] = lds32(qb + kt * 32 + 8 * KP2 + 16);
        }
    }
    __syncthreads();   // Q region free for pipeline reuse

    float O[8][4] = {};
    float m[2] = {-1e30f, -1e30f};
    float l[2] = {0.0f, 0.0f};     // lane-partial; reduced at the end

    for (int jb = 0; jb < nblk; ++jb) {
        const uint32_t stg = sb + (uint32_t)(jb & 1) * ASTGB;
        if (jb + 1 < nblk) {
            load_kv_tile(sb + (uint32_t)((jb + 1) & 1) * ASTGB, bh, (jb + 1) * 128, tid);
            CP_COMMIT();
            CP_WAIT(1);
        } else {
            CP_WAIT(0);
        }
        __syncthreads();

        // ----- S = Q K^T over 128 keys (single fp16, SCALE pre-folded) -----
        float S[16][4] = {};
        #pragma unroll
        for (int kt = 0; kt < 4; ++kt) {
            const uint32_t kb = stg + K_O + (uint32_t)g * KP2 + kt * 32 + c * 4;
            #pragma unroll
            for (int nt = 0; nt < 16; ++nt) {
                const uint32_t a0 = kb + nt * 8 * KP2;
                const uint32_t b0 = lds32(a0);
                const uint32_t b1 = lds32(a0 + 16);
                mma16816h(S[nt], qhf[kt], b0, b1);
            }
        }

        // ----- causal mask (diagonal block only) -----
        if (jb == nblk - 1) {
            #pragma unroll
            for (int nt = 0; nt < 16; ++nt) {
                #pragma unroll
                for (int e = 0; e < 4; ++e) {
                    const int gk = jb * 128 + nt * 8 + 2 * c + (e & 1);
                    const int gr = qi * 64 + moff + g + ((e >> 1) << 3);
                    if (gk > gr) S[nt][e] = -1e30f;
                }
            }
        }

        // ----- online softmax over 128 cols -----
        float rowm[2] = {-1e30f, -1e30f};
        #pragma unroll
        for (int nt = 0; nt < 16; ++nt) {
            rowm[0] = fmaxf(rowm[0], fmaxf(S[nt][0], S[nt][1]));
            rowm[1] = fmaxf(rowm[1], fmaxf(S[nt][2], S[nt][3]));
        }
        #pragma unroll
        for (int r = 0; r < 2; ++r) {
            rowm[r] = fmaxf(rowm[r], __shfl_xor_sync(0xffffffffu, rowm[r], 1));
            rowm[r] = fmaxf(rowm[r], __shfl_xor_sync(0xffffffffu, rowm[r], 2));
        }
        float corr[2];
        #pragma unroll
        for (int r = 0; r < 2; ++r) {
            const float mnew = fmaxf(m[r], rowm[r]);
            corr[r] = fexp(m[r] - mnew);
            l[r] *= corr[r];
            m[r] = mnew;
        }
        #pragma unroll
        for (int nt = 0; nt < 8; ++nt) {
            O[nt][0] *= corr[0]; O[nt][1] *= corr[0];
            O[nt][2] *= corr[1]; O[nt][3] *= corr[1];
        }
        #pragma unroll
        for (int nt = 0; nt < 16; ++nt) {
            #pragma unroll
            for (int e = 0; e < 4; ++e) {
                const float p = fexp(S[nt][e] - m[e >> 1]);
                S[nt][e] = p;
                l[e >> 1] += p;          // lane-partial accumulation
            }
        }

        // ----- P -> single fp16 A-fragments (8 key-chunks of 16) -----
        uint32_t pfp[8][4];
        #pragma unroll
        for (int t = 0; t < 16; ++t) {
            const int kt = t >> 1;
            const int sl = (t & 1) << 1;
            pfp[kt][sl + 0] = pack_h2(S[t][0], S[t][1]);
            pfp[kt][sl + 1] = pack_h2(S[t][2], S[t][3]);
        }

        // ----- O += P V (single fp16, 128 keys) -----
        #pragma unroll
        for (int kt = 0; kt < 8; ++kt) {
            const uint32_t vb = stg + V_O + (uint32_t)g * VP2 + kt * 32 + c * 4;
            #pragma unroll
            for (int nt = 0; nt < 8; ++nt) {
                const uint32_t a0 = vb + nt * 8 * VP2;
                const uint32_t b0 = lds32(a0);
                const uint32_t b1 = lds32(a0 + 16);
                mma16816h(O[nt], pfp[kt], b0, b1);
            }
        }
        __syncthreads();
    }

    // ----- reduce lane-partial l, normalize, write out [B, L, D] -----
    #pragma unroll
    for (int r = 0; r < 2; ++r) {
        l[r] += __shfl_xor_sync(0xffffffffu, l[r], 1);
        l[r] += __shfl_xor_sync(0xffffffffu, l[r], 2);
    }
    const float inv0 = 1.0f / l[0];
    const float inv1 = 1.0f / l[1];
    const int row0 = qi * 64 + moff + g;
    #pragma unroll
    for (int nt = 0; nt < 8; ++nt) {
        const int col = h * HDIM + nt * 8 + 2 * c;
        float2 v0 = {O[nt][0] * inv0, O[nt][1] * inv0};
        float2 v1 = {O[nt][2] * inv1, O[nt][3] * inv1};
        *(float2*)&out[((size_t)b * SEQ + row0) * DMODEL + col] = v0;
        *(float2*)&out[((size_t)b * SEQ + row0 + 8) * DMODEL + col] = v1;
    }
}

// ---------------------------------------------------------------------------
extern "C" void kernel_launch(void* const* d_in, const int* in_sizes, int n_in,
                              void* d_out, int out_size)
{
    const float* X  = (const float*)d_in[0];
    const float* Wq = (const float*)d_in[1];
    const float* bq = (const float*)d_in[2];
    const float* Wk = (const float*)d_in[3];
    const float* bk = (const float*)d_in[4];
    const float* Wv = (const float*)d_in[5];
    const float* bv = (const float*)d_in[6];
    float* out = (float*)d_out;

    prep_kernel<<<8192 + 3 * 1024, 256>>>(X, Wq, Wk, Wv);

    cudaFuncSetAttribute(gemm_kernel, cudaFuncAttributeMaxDynamicSharedMemorySize,
                         GEMM_SMEM);
    dim3 gg((BATCH * SEQ) / 128, DMODEL / 128, 3);
    gemm_kernel<<<gg, 256, GEMM_SMEM>>>(bq, bk, bv);

    cudaFuncSetAttribute(attn_kernel, cudaFuncAttributeMaxDynamicSharedMemorySize,
                         ATT_SMEM);
    dim3 ag(SEQ / 64, BATCH * NHEAD);
    attn_kernel<<<ag, 128, ATT_SMEM>>>(out);
}